// round 1
// baseline (speedup 1.0000x reference)
#include <cuda_runtime.h>
#include <math.h>

#define NROWS 8192
#define DDIM  512
#define TS    128
#define KT    8
#define NBLK  (NROWS / TS)   // 64 column-blocks in similarity partials

// ---------------- device scratch (no allocations allowed) ----------------
__device__ float g_T [NROWS * DDIM];   // layer-1 output (elu)
__device__ float g_H [NROWS * DDIM];   // layer-2 output (pre-normalize)
__device__ float g_N1[NROWS * DDIM];   // normalized h1
__device__ float g_N2[NROWS * DDIM];   // normalized h2
__device__ float g_rs11p[NROWS * NBLK];
__device__ float g_rs22p[NROWS * NBLK];
__device__ float g_rs12p[NROWS * NBLK];
__device__ float g_cs12p[NROWS * NBLK];
__device__ float g_d12 [NROWS];
__device__ float g_loss[NROWS];

// ---------------- shared 128x128 / 8x8-per-thread fp32 GEMM core ----------
// C_tile = A_rows(rb*128..)  dot  B_rows(cb*128..)   (both K-contiguous, NT)
__device__ __forceinline__ void gemm_tile_nt(const float* __restrict__ Ag,
                                             const float* __restrict__ Bg,
                                             float* smem,
                                             float (&acc)[8][8],
                                             int tx, int ty, int t) {
    float* As = smem;               // [KT][TS] K-major
    float* Bs = smem + KT * TS;     // [KT][TS] K-major

    const int lrow = t >> 1;          // 0..127
    const int lcol = (t & 1) << 2;    // 0 or 4
    const float* ap = Ag + (size_t)lrow * DDIM + lcol;
    const float* bp = Bg + (size_t)lrow * DDIM + lcol;

    for (int kt = 0; kt < DDIM; kt += KT) {
        float4 av = *(const float4*)(ap + kt);
        float4 bv = *(const float4*)(bp + kt);
        __syncthreads();   // previous iteration's compute finished
        As[(lcol + 0) * TS + lrow] = av.x;
        As[(lcol + 1) * TS + lrow] = av.y;
        As[(lcol + 2) * TS + lrow] = av.z;
        As[(lcol + 3) * TS + lrow] = av.w;
        Bs[(lcol + 0) * TS + lrow] = bv.x;
        Bs[(lcol + 1) * TS + lrow] = bv.y;
        Bs[(lcol + 2) * TS + lrow] = bv.z;
        Bs[(lcol + 3) * TS + lrow] = bv.w;
        __syncthreads();
#pragma unroll
        for (int k = 0; k < KT; k++) {
            float4 a0 = *(const float4*)(As + k * TS + ty * 8);
            float4 a1 = *(const float4*)(As + k * TS + ty * 8 + 4);
            float4 b0 = *(const float4*)(Bs + k * TS + tx * 8);
            float4 b1 = *(const float4*)(Bs + k * TS + tx * 8 + 4);
            float a[8] = {a0.x, a0.y, a0.z, a0.w, a1.x, a1.y, a1.z, a1.w};
            float b[8] = {b0.x, b0.y, b0.z, b0.w, b1.x, b1.y, b1.z, b1.w};
#pragma unroll
            for (int i = 0; i < 8; i++)
#pragma unroll
                for (int j = 0; j < 8; j++)
                    acc[i][j] += a[i] * b[j];
        }
    }
}

// ---------------- projection GEMM: out = act(A @ W^T + b) -----------------
template <bool DO_ELU>
__global__ void __launch_bounds__(256)
proj_kernel(const float* __restrict__ A, const float* __restrict__ W,
            const float* __restrict__ bias, float* __restrict__ out) {
    __shared__ float smem[2 * KT * TS];
    const int rb = blockIdx.y, cb = blockIdx.x;
    const int t = threadIdx.x, tx = t & 15, ty = t >> 4;
    float acc[8][8] = {};
    gemm_tile_nt(A + (size_t)rb * TS * DDIM, W + (size_t)cb * TS * DDIM,
                 smem, acc, tx, ty, t);
#pragma unroll
    for (int i = 0; i < 8; i++) {
        const int r = rb * TS + ty * 8 + i;
        const int c = cb * TS + tx * 8;
        float4 v0, v1;
        float v[8];
#pragma unroll
        for (int j = 0; j < 8; j++) {
            float x = acc[i][j] + bias[c + j];
            if (DO_ELU) x = (x > 0.0f) ? x : expm1f(x);
            v[j] = x;
        }
        v0 = make_float4(v[0], v[1], v[2], v[3]);
        v1 = make_float4(v[4], v[5], v[6], v[7]);
        *(float4*)(out + (size_t)r * DDIM + c)     = v0;
        *(float4*)(out + (size_t)r * DDIM + c + 4) = v1;
    }
}

// ---------------- similarity tile: exp((A·B^T)/tau), row/col sums ---------
template <bool COLSUM>
__global__ void __launch_bounds__(256)
sim_kernel(const float* __restrict__ A, const float* __restrict__ B,
           float* __restrict__ rspart, float* __restrict__ cspart) {
    __shared__ float smem[2 * KT * TS];   // 2048 floats, reused as red[128][16]
    const int rb = blockIdx.y, cb = blockIdx.x;
    const int t = threadIdx.x, tx = t & 15, ty = t >> 4;
    float acc[8][8] = {};
    gemm_tile_nt(A + (size_t)rb * TS * DDIM, B + (size_t)cb * TS * DDIM,
                 smem, acc, tx, ty, t);

    float rsum[8] = {}, csum[8] = {};
#pragma unroll
    for (int i = 0; i < 8; i++)
#pragma unroll
        for (int j = 0; j < 8; j++) {
            float e = __expf(acc[i][j] * 2.0f);   // 1/tau = 2
            rsum[i] += e;
            csum[j] += e;
        }

    float* red = smem;
    __syncthreads();
#pragma unroll
    for (int i = 0; i < 8; i++) red[(ty * 8 + i) * 16 + tx] = rsum[i];
    __syncthreads();
    if (t < TS) {
        float s = 0.0f;
#pragma unroll
        for (int m = 0; m < 16; m++) s += red[t * 16 + m];
        rspart[(size_t)(rb * TS + t) * NBLK + cb] = s;
    }
    if (COLSUM) {
        __syncthreads();
#pragma unroll
        for (int j = 0; j < 8; j++) red[(tx * 8 + j) * 16 + ty] = csum[j];
        __syncthreads();
        if (t < TS) {
            float s = 0.0f;
#pragma unroll
            for (int m = 0; m < 16; m++) s += red[t * 16 + m];
            cspart[(size_t)(cb * TS + t) * NBLK + rb] = s;
        }
    }
}

// ---------------- row L2-normalize (one warp per row) ---------------------
__global__ void __launch_bounds__(256)
normalize_kernel(const float* __restrict__ H, float* __restrict__ O) {
    const int row  = blockIdx.x * 8 + (threadIdx.x >> 5);
    const int lane = threadIdx.x & 31;
    const float4* hp = (const float4*)(H + (size_t)row * DDIM);
    float4* op = (float4*)(O + (size_t)row * DDIM);
    float4 v[4];
    float ss = 0.0f;
#pragma unroll
    for (int m = 0; m < 4; m++) {
        v[m] = hp[lane + 32 * m];
        ss += v[m].x * v[m].x + v[m].y * v[m].y + v[m].z * v[m].z + v[m].w * v[m].w;
    }
#pragma unroll
    for (int o = 16; o > 0; o >>= 1) ss += __shfl_xor_sync(0xffffffffu, ss, o);
    const float inv = 1.0f / fmaxf(sqrtf(ss), 1e-12f);
#pragma unroll
    for (int m = 0; m < 4; m++) {
        float4 w = v[m];
        w.x *= inv; w.y *= inv; w.z *= inv; w.w *= inv;
        op[lane + 32 * m] = w;
    }
}

// ---------------- diag(n1 · n2) per row ------------------------------------
__global__ void __launch_bounds__(256)
d12_kernel(const float* __restrict__ N1, const float* __restrict__ N2,
           float* __restrict__ d12) {
    const int row  = blockIdx.x * 8 + (threadIdx.x >> 5);
    const int lane = threadIdx.x & 31;
    const float4* a = (const float4*)(N1 + (size_t)row * DDIM);
    const float4* b = (const float4*)(N2 + (size_t)row * DDIM);
    float s = 0.0f;
#pragma unroll
    for (int m = 0; m < 4; m++) {
        float4 x = a[lane + 32 * m], y = b[lane + 32 * m];
        s += x.x * y.x + x.y * y.y + x.z * y.z + x.w * y.w;
    }
#pragma unroll
    for (int o = 16; o > 0; o >>= 1) s += __shfl_xor_sync(0xffffffffu, s, o);
    if (lane == 0) d12[row] = s;
}

// ---------------- per-row loss from partials -------------------------------
__global__ void __launch_bounds__(256)
rowloss_kernel(const float* __restrict__ rs11p, const float* __restrict__ rs22p,
               const float* __restrict__ rs12p, const float* __restrict__ cs12p,
               const float* __restrict__ d12, float* __restrict__ loss) {
    const int row  = blockIdx.x * 8 + (threadIdx.x >> 5);
    const int lane = threadIdx.x & 31;
    float s11 = 0.0f, s22 = 0.0f, s12 = 0.0f, c12 = 0.0f;
    for (int m = lane; m < NBLK; m += 32) {
        const size_t o = (size_t)row * NBLK + m;
        s11 += rs11p[o];
        s22 += rs22p[o];
        s12 += rs12p[o];
        c12 += cs12p[o];
    }
#pragma unroll
    for (int o = 16; o > 0; o >>= 1) {
        s11 += __shfl_xor_sync(0xffffffffu, s11, o);
        s22 += __shfl_xor_sync(0xffffffffu, s22, o);
        s12 += __shfl_xor_sync(0xffffffffu, s12, o);
        c12 += __shfl_xor_sync(0xffffffffu, c12, o);
    }
    if (lane == 0) {
        const float E2 = 7.38905609893065f;   // exp(1/tau), diag of refl
        const float den1 = s11 + s12 - E2;
        const float den2 = s22 + c12 - E2;
        loss[row] = -2.0f * d12[row] + 0.5f * (__logf(den1) + __logf(den2));
    }
}

// ---------------- final mean (single block, deterministic) -----------------
__global__ void __launch_bounds__(1024)
final_kernel(const float* __restrict__ loss, float* __restrict__ out) {
    __shared__ float sm[1024];
    const int t = threadIdx.x;
    float s = 0.0f;
    for (int i = t; i < NROWS; i += 1024) s += loss[i];
    sm[t] = s;
    __syncthreads();
    for (int o = 512; o > 0; o >>= 1) {
        if (t < o) sm[t] += sm[t + o];
        __syncthreads();
    }
    if (t == 0) out[0] = sm[0] * (1.0f / NROWS);
}

// ---------------- launch ----------------------------------------------------
extern "C" void kernel_launch(void* const* d_in, const int* in_sizes, int n_in,
                              void* d_out, int out_size) {
    const float* pri = (const float*)d_in[0];
    const float* aux = (const float*)d_in[1];
    const float* W1  = (const float*)d_in[2];
    const float* b1  = (const float*)d_in[3];
    const float* W2  = (const float*)d_in[4];
    const float* b2  = (const float*)d_in[5];
    float* out = (float*)d_out;

    float *T, *H, *N1, *N2, *rs11p, *rs22p, *rs12p, *cs12p, *d12, *loss;
    cudaGetSymbolAddress((void**)&T,     g_T);
    cudaGetSymbolAddress((void**)&H,     g_H);
    cudaGetSymbolAddress((void**)&N1,    g_N1);
    cudaGetSymbolAddress((void**)&N2,    g_N2);
    cudaGetSymbolAddress((void**)&rs11p, g_rs11p);
    cudaGetSymbolAddress((void**)&rs22p, g_rs22p);
    cudaGetSymbolAddress((void**)&rs12p, g_rs12p);
    cudaGetSymbolAddress((void**)&cs12p, g_cs12p);
    cudaGetSymbolAddress((void**)&d12,   g_d12);
    cudaGetSymbolAddress((void**)&loss,  g_loss);

    const dim3 pg(DDIM / TS, NROWS / TS);   // (4, 64)
    const dim3 sg(NBLK, NBLK);              // (64, 64)

    // projection(pri) -> N1
    proj_kernel<true ><<<pg, 256>>>(pri, W1, b1, T);
    proj_kernel<false><<<pg, 256>>>(T,   W2, b2, H);
    normalize_kernel<<<NROWS / 8, 256>>>(H, N1);
    // projection(aux) -> N2
    proj_kernel<true ><<<pg, 256>>>(aux, W1, b1, T);
    proj_kernel<false><<<pg, 256>>>(T,   W2, b2, H);
    normalize_kernel<<<NROWS / 8, 256>>>(H, N2);

    d12_kernel<<<NROWS / 8, 256>>>(N1, N2, d12);

    sim_kernel<false><<<sg, 256>>>(N1, N1, rs11p, nullptr);
    sim_kernel<false><<<sg, 256>>>(N2, N2, rs22p, nullptr);
    sim_kernel<true ><<<sg, 256>>>(N1, N2, rs12p, cs12p);

    rowloss_kernel<<<NROWS / 8, 256>>>(rs11p, rs22p, rs12p, cs12p, d12, loss);
    final_kernel<<<1, 1024>>>(loss, out);
}

// round 3
// speedup vs baseline: 4.2146x; 4.2146x over previous
#include <cuda_runtime.h>
#include <cuda_bf16.h>
#include <math.h>
#include <stdint.h>

#define NROWS 8192
#define DDIM  512
#define TS    128
#define KT    8
#define NBLK  (NROWS / TS)   // 64 column-blocks in similarity partials

// ---------------- device scratch (no allocations allowed) ----------------
__device__ float g_T [NROWS * DDIM];
__device__ float g_H [NROWS * DDIM];
__device__ float g_N1[NROWS * DDIM];
__device__ float g_N2[NROWS * DDIM];
__device__ __nv_bfloat16 g_B1[NROWS * DDIM];
__device__ __nv_bfloat16 g_B2[NROWS * DDIM];
__device__ float g_rs11p[NROWS * NBLK];
__device__ float g_rs22p[NROWS * NBLK];
__device__ float g_rs12p[NROWS * NBLK];
__device__ float g_cs12p[NROWS * NBLK];
__device__ float g_d12 [NROWS];
__device__ float g_loss[NROWS];

// ====================== helpers ======================
__device__ __forceinline__ uint32_t smem_u32(const void* p) {
    uint32_t a;
    asm("{ .reg .u64 t; cvta.to.shared.u64 t, %1; cvt.u32.u64 %0, t; }"
        : "=r"(a) : "l"(p));
    return a;
}
__device__ __forceinline__ void ldsm_x4(uint32_t (&r)[4], uint32_t addr) {
    asm volatile("ldmatrix.sync.aligned.m8n8.x4.shared.b16 {%0,%1,%2,%3}, [%4];"
        : "=r"(r[0]), "=r"(r[1]), "=r"(r[2]), "=r"(r[3]) : "r"(addr));
}
__device__ __forceinline__ void mma16816(float (&d)[4], const uint32_t (&a)[4],
                                         uint32_t b0, uint32_t b1) {
    asm volatile("mma.sync.aligned.m16n8k16.row.col.f32.bf16.bf16.f32 "
        "{%0,%1,%2,%3}, {%4,%5,%6,%7}, {%8,%9}, {%0,%1,%2,%3};"
        : "+f"(d[0]), "+f"(d[1]), "+f"(d[2]), "+f"(d[3])
        : "r"(a[0]), "r"(a[1]), "r"(a[2]), "r"(a[3]), "r"(b0), "r"(b1));
}
__device__ __forceinline__ float fast_exp2(float x) {
    float y; asm("ex2.approx.f32 %0, %1;" : "=f"(y) : "f"(x)); return y;
}

// ================= mma.sync similarity kernel =================
// Per 128x128 tile of exp(2 * A_tile · B_tile^T): row-sum partials
// (and col-sum partials if COLSUM).  A, B bf16 row-major [8192, 512].
#define LDAB 80   // smem row stride (bytes) for 32 bf16 + pad, 16B-aligned

template <bool COLSUM>
__global__ void __launch_bounds__(256, 2)
sim_mma_kernel(const __nv_bfloat16* __restrict__ A, const __nv_bfloat16* __restrict__ B,
               float* __restrict__ rspart, float* __restrict__ cspart) {
    __shared__ __align__(128) char sm[2 * 128 * LDAB];   // A chunk | B chunk
    const uint32_t sA = smem_u32(sm);
    const uint32_t sB = sA + 128 * LDAB;

    const int tid    = threadIdx.x;
    const int lane   = tid & 31;
    const int wid    = tid >> 5;
    const int warp_m = wid & 3;     // 4 warps along M (32 rows each)
    const int warp_n = wid >> 2;    // 2 warps along N (64 cols each)
    const int rb = blockIdx.y, cb = blockIdx.x;

    const char* Ag = (const char*)(A + (size_t)rb * TS * DDIM);
    const char* Bg = (const char*)(B + (size_t)cb * TS * DDIM);

    // per-thread copy offsets (2 uint4 per matrix per chunk)
    const int r0 = tid >> 2, p0 = tid & 3;        // row 0..63, 16B part
    // ldmatrix per-lane address components
    const int q  = lane >> 3, rr = lane & 7;
    const uint32_t lds_row_off = (uint32_t)(((q & 1) * 8 + rr) * LDAB + (q >> 1) * 16);
    const uint32_t a_base = sA + (uint32_t)(warp_m * 32) * LDAB + lds_row_off;
    const uint32_t b_base = sB + (uint32_t)(warp_n * 64) * LDAB + lds_row_off;

    float acc[2][8][4] = {};

    for (int kc = 0; kc < 16; kc++) {
        __syncthreads();   // previous chunk's ldmatrix done
        {
            const size_t g0 = (size_t)r0 * (DDIM * 2) + (size_t)kc * 64 + p0 * 16;
            const size_t g1 = g0 + (size_t)64 * (DDIM * 2);
            uint4 va0 = *(const uint4*)(Ag + g0);
            uint4 va1 = *(const uint4*)(Ag + g1);
            uint4 vb0 = *(const uint4*)(Bg + g0);
            uint4 vb1 = *(const uint4*)(Bg + g1);
            const uint32_t s0 = (uint32_t)(r0 * LDAB + p0 * 16);
            const uint32_t s1 = s0 + 64 * LDAB;
            *(uint4*)(sm + s0)              = va0;
            *(uint4*)(sm + s1)              = va1;
            *(uint4*)(sm + 128 * LDAB + s0) = vb0;
            *(uint4*)(sm + 128 * LDAB + s1) = vb1;
        }
        __syncthreads();

#pragma unroll
        for (int kk = 0; kk < 2; kk++) {
            uint32_t af[2][4];
            ldsm_x4(af[0], a_base + kk * 32);
            ldsm_x4(af[1], a_base + 16 * LDAB + kk * 32);
            uint32_t bf[4][4];
#pragma unroll
            for (int n2 = 0; n2 < 4; n2++)
                ldsm_x4(bf[n2], b_base + n2 * 16 * LDAB + kk * 32);
#pragma unroll
            for (int mt = 0; mt < 2; mt++)
#pragma unroll
                for (int nt = 0; nt < 8; nt++)
                    mma16816(acc[mt][nt], af[mt],
                             bf[nt >> 1][nt & 1], bf[nt >> 1][(nt & 1) + 2]);
        }
    }
    __syncthreads();   // all ldmatrix done; smem reusable for reductions

    float* rs_sm = (float*)sm;            // [128][2]
    float* cs_sm = (float*)(sm + 1024);   // [4][128]

    // exp + per-thread accumulation
    const float C = 2.8853900817779268f;  // 2 / ln 2
    float rs_acc[2][2] = {};
    float cs2[8][2];
    if (COLSUM)
#pragma unroll
        for (int nt = 0; nt < 8; nt++) cs2[nt][0] = cs2[nt][1] = 0.0f;

#pragma unroll
    for (int mt = 0; mt < 2; mt++)
#pragma unroll
        for (int nt = 0; nt < 8; nt++) {
            float e0 = fast_exp2(acc[mt][nt][0] * C);
            float e1 = fast_exp2(acc[mt][nt][1] * C);
            float e2 = fast_exp2(acc[mt][nt][2] * C);
            float e3 = fast_exp2(acc[mt][nt][3] * C);
            rs_acc[mt][0] += e0 + e1;
            rs_acc[mt][1] += e2 + e3;
            if (COLSUM) {
                cs2[nt][0] += e0 + e2;
                cs2[nt][1] += e1 + e3;
            }
        }

    // row sums: reduce over t%4 (cols), then across warp_n via smem
#pragma unroll
    for (int mt = 0; mt < 2; mt++)
#pragma unroll
        for (int half = 0; half < 2; half++) {
            float v = rs_acc[mt][half];
            v += __shfl_xor_sync(0xffffffffu, v, 1);
            v += __shfl_xor_sync(0xffffffffu, v, 2);
            if ((lane & 3) == 0) {
                int row = warp_m * 32 + mt * 16 + half * 8 + (lane >> 2);
                rs_sm[row * 2 + warp_n] = v;
            }
        }
    if (COLSUM) {
#pragma unroll
        for (int nt = 0; nt < 8; nt++)
#pragma unroll
            for (int e = 0; e < 2; e++) {
                float v = cs2[nt][e];
                v += __shfl_xor_sync(0xffffffffu, v, 4);
                v += __shfl_xor_sync(0xffffffffu, v, 8);
                v += __shfl_xor_sync(0xffffffffu, v, 16);
                if (lane < 4) {
                    int col = warp_n * 64 + nt * 8 + lane * 2 + e;
                    cs_sm[warp_m * 128 + col] = v;
                }
            }
    }
    __syncthreads();

    if (tid < TS) {
        float rtot = rs_sm[tid * 2 + 0] + rs_sm[tid * 2 + 1];
        rspart[(size_t)(rb * TS + tid) * NBLK + cb] = rtot;
        if (COLSUM) {
            float ctot = cs_sm[0 * 128 + tid] + cs_sm[1 * 128 + tid] +
                         cs_sm[2 * 128 + tid] + cs_sm[3 * 128 + tid];
            cspart[(size_t)(cb * TS + tid) * NBLK + rb] = ctot;
        }
    }
}

// ---------------- shared 128x128 / 8x8-per-thread fp32 GEMM core ----------
__device__ __forceinline__ void gemm_tile_nt(const float* __restrict__ Ag,
                                             const float* __restrict__ Bg,
                                             float* smem,
                                             float (&acc)[8][8],
                                             int tx, int ty, int t) {
    float* As = smem;
    float* Bs = smem + KT * TS;
    const int lrow = t >> 1;
    const int lcol = (t & 1) << 2;
    const float* ap = Ag + (size_t)lrow * DDIM + lcol;
    const float* bp = Bg + (size_t)lrow * DDIM + lcol;

    for (int kt = 0; kt < DDIM; kt += KT) {
        float4 av = *(const float4*)(ap + kt);
        float4 bv = *(const float4*)(bp + kt);
        __syncthreads();
        As[(lcol + 0) * TS + lrow] = av.x;
        As[(lcol + 1) * TS + lrow] = av.y;
        As[(lcol + 2) * TS + lrow] = av.z;
        As[(lcol + 3) * TS + lrow] = av.w;
        Bs[(lcol + 0) * TS + lrow] = bv.x;
        Bs[(lcol + 1) * TS + lrow] = bv.y;
        Bs[(lcol + 2) * TS + lrow] = bv.z;
        Bs[(lcol + 3) * TS + lrow] = bv.w;
        __syncthreads();
#pragma unroll
        for (int k = 0; k < KT; k++) {
            float4 a0 = *(const float4*)(As + k * TS + ty * 8);
            float4 a1 = *(const float4*)(As + k * TS + ty * 8 + 4);
            float4 b0 = *(const float4*)(Bs + k * TS + tx * 8);
            float4 b1 = *(const float4*)(Bs + k * TS + tx * 8 + 4);
            float a[8] = {a0.x, a0.y, a0.z, a0.w, a1.x, a1.y, a1.z, a1.w};
            float b[8] = {b0.x, b0.y, b0.z, b0.w, b1.x, b1.y, b1.z, b1.w};
#pragma unroll
            for (int i = 0; i < 8; i++)
#pragma unroll
                for (int j = 0; j < 8; j++)
                    acc[i][j] += a[i] * b[j];
        }
    }
}

template <bool DO_ELU>
__global__ void __launch_bounds__(256)
proj_kernel(const float* __restrict__ A, const float* __restrict__ W,
            const float* __restrict__ bias, float* __restrict__ out) {
    __shared__ float smem[2 * KT * TS];
    const int rb = blockIdx.y, cb = blockIdx.x;
    const int t = threadIdx.x, tx = t & 15, ty = t >> 4;
    float acc[8][8] = {};
    gemm_tile_nt(A + (size_t)rb * TS * DDIM, W + (size_t)cb * TS * DDIM,
                 smem, acc, tx, ty, t);
#pragma unroll
    for (int i = 0; i < 8; i++) {
        const int rr = rb * TS + ty * 8 + i;
        const int c = cb * TS + tx * 8;
        float v[8];
#pragma unroll
        for (int j = 0; j < 8; j++) {
            float x = acc[i][j] + bias[c + j];
            if (DO_ELU) x = (x > 0.0f) ? x : expm1f(x);
            v[j] = x;
        }
        *(float4*)(out + (size_t)rr * DDIM + c)     = make_float4(v[0], v[1], v[2], v[3]);
        *(float4*)(out + (size_t)rr * DDIM + c + 4) = make_float4(v[4], v[5], v[6], v[7]);
    }
}

// ---------------- row L2-normalize -> fp32 + bf16 outputs -----------------
__global__ void __launch_bounds__(256)
normalize_kernel(const float* __restrict__ H, float* __restrict__ O,
                 __nv_bfloat16* __restrict__ Ob) {
    const int row  = blockIdx.x * 8 + (threadIdx.x >> 5);
    const int lane = threadIdx.x & 31;
    const float4* hp = (const float4*)(H + (size_t)row * DDIM);
    float4* op = (float4*)(O + (size_t)row * DDIM);
    float4 v[4];
    float ss = 0.0f;
#pragma unroll
    for (int m = 0; m < 4; m++) {
        v[m] = hp[lane + 32 * m];
        ss += v[m].x * v[m].x + v[m].y * v[m].y + v[m].z * v[m].z + v[m].w * v[m].w;
    }
#pragma unroll
    for (int o = 16; o > 0; o >>= 1) ss += __shfl_xor_sync(0xffffffffu, ss, o);
    const float inv = 1.0f / fmaxf(sqrtf(ss), 1e-12f);
#pragma unroll
    for (int m = 0; m < 4; m++) {
        float4 w = v[m];
        w.x *= inv; w.y *= inv; w.z *= inv; w.w *= inv;
        op[lane + 32 * m] = w;
        __nv_bfloat162 p0 = __floats2bfloat162_rn(w.x, w.y);
        __nv_bfloat162 p1 = __floats2bfloat162_rn(w.z, w.w);
        uint2 pk = make_uint2(*(uint32_t*)&p0, *(uint32_t*)&p1);
        *(uint2*)(Ob + (size_t)row * DDIM + (lane + 32 * m) * 4) = pk;
    }
}

__global__ void __launch_bounds__(256)
d12_kernel(const float* __restrict__ N1, const float* __restrict__ N2,
           float* __restrict__ d12) {
    const int row  = blockIdx.x * 8 + (threadIdx.x >> 5);
    const int lane = threadIdx.x & 31;
    const float4* a = (const float4*)(N1 + (size_t)row * DDIM);
    const float4* b = (const float4*)(N2 + (size_t)row * DDIM);
    float s = 0.0f;
#pragma unroll
    for (int m = 0; m < 4; m++) {
        float4 x = a[lane + 32 * m], y = b[lane + 32 * m];
        s += x.x * y.x + x.y * y.y + x.z * y.z + x.w * y.w;
    }
#pragma unroll
    for (int o = 16; o > 0; o >>= 1) s += __shfl_xor_sync(0xffffffffu, s, o);
    if (lane == 0) d12[row] = s;
}

__global__ void __launch_bounds__(256)
rowloss_kernel(const float* __restrict__ rs11p, const float* __restrict__ rs22p,
               const float* __restrict__ rs12p, const float* __restrict__ cs12p,
               const float* __restrict__ d12, float* __restrict__ loss) {
    const int row  = blockIdx.x * 8 + (threadIdx.x >> 5);
    const int lane = threadIdx.x & 31;
    float s11 = 0.0f, s22 = 0.0f, s12 = 0.0f, c12 = 0.0f;
    for (int m = lane; m < NBLK; m += 32) {
        const size_t o = (size_t)row * NBLK + m;
        s11 += rs11p[o];
        s22 += rs22p[o];
        s12 += rs12p[o];
        c12 += cs12p[o];
    }
#pragma unroll
    for (int o = 16; o > 0; o >>= 1) {
        s11 += __shfl_xor_sync(0xffffffffu, s11, o);
        s22 += __shfl_xor_sync(0xffffffffu, s22, o);
        s12 += __shfl_xor_sync(0xffffffffu, s12, o);
        c12 += __shfl_xor_sync(0xffffffffu, c12, o);
    }
    if (lane == 0) {
        const float E2 = 7.38905609893065f;   // exp(1/tau)
        const float den1 = s11 + s12 - E2;
        const float den2 = s22 + c12 - E2;
        loss[row] = -2.0f * d12[row] + 0.5f * (__logf(den1) + __logf(den2));
    }
}

__global__ void __launch_bounds__(1024)
final_kernel(const float* __restrict__ loss, float* __restrict__ out) {
    __shared__ float sm[1024];
    const int t = threadIdx.x;
    float s = 0.0f;
    for (int i = t; i < NROWS; i += 1024) s += loss[i];
    sm[t] = s;
    __syncthreads();
    for (int o = 512; o > 0; o >>= 1) {
        if (t < o) sm[t] += sm[t + o];
        __syncthreads();
    }
    if (t == 0) out[0] = sm[0] * (1.0f / NROWS);
}

// ---------------- launch ----------------------------------------------------
extern "C" void kernel_launch(void* const* d_in, const int* in_sizes, int n_in,
                              void* d_out, int out_size) {
    const float* pri = (const float*)d_in[0];
    const float* aux = (const float*)d_in[1];
    const float* W1  = (const float*)d_in[2];
    const float* b1  = (const float*)d_in[3];
    const float* W2  = (const float*)d_in[4];
    const float* b2  = (const float*)d_in[5];
    float* out = (float*)d_out;

    float *T, *H, *N1, *N2, *rs11p, *rs22p, *rs12p, *cs12p, *d12, *loss;
    __nv_bfloat16 *B1, *B2;
    cudaGetSymbolAddress((void**)&T,     g_T);
    cudaGetSymbolAddress((void**)&H,     g_H);
    cudaGetSymbolAddress((void**)&N1,    g_N1);
    cudaGetSymbolAddress((void**)&N2,    g_N2);
    cudaGetSymbolAddress((void**)&B1,    g_B1);
    cudaGetSymbolAddress((void**)&B2,    g_B2);
    cudaGetSymbolAddress((void**)&rs11p, g_rs11p);
    cudaGetSymbolAddress((void**)&rs22p, g_rs22p);
    cudaGetSymbolAddress((void**)&rs12p, g_rs12p);
    cudaGetSymbolAddress((void**)&cs12p, g_cs12p);
    cudaGetSymbolAddress((void**)&d12,   g_d12);
    cudaGetSymbolAddress((void**)&loss,  g_loss);

    const dim3 pg(DDIM / TS, NROWS / TS);   // (4, 64)
    const dim3 sg(NBLK, NBLK);              // (64, 64)

    proj_kernel<true ><<<pg, 256>>>(pri, W1, b1, T);
    proj_kernel<false><<<pg, 256>>>(T,   W2, b2, H);
    normalize_kernel<<<NROWS / 8, 256>>>(H, N1, B1);
    proj_kernel<true ><<<pg, 256>>>(aux, W1, b1, T);
    proj_kernel<false><<<pg, 256>>>(T,   W2, b2, H);
    normalize_kernel<<<NROWS / 8, 256>>>(H, N2, B2);

    d12_kernel<<<NROWS / 8, 256>>>(N1, N2, d12);

    sim_mma_kernel<false><<<sg, 256>>>(B1, B1, rs11p, nullptr);
    sim_mma_kernel<false><<<sg, 256>>>(B2, B2, rs22p, nullptr);
    sim_mma_kernel<true ><<<sg, 256>>>(B1, B2, rs12p, cs12p);

    rowloss_kernel<<<NROWS / 8, 256>>>(rs11p, rs22p, rs12p, cs12p, d12, loss);
    final_kernel<<<1, 1024>>>(loss, out);
}

// round 4
// speedup vs baseline: 6.7137x; 1.5930x over previous
#include <cuda_runtime.h>
#include <cuda_bf16.h>
#include <math.h>
#include <stdint.h>

#define NROWS 8192
#define DDIM  512
#define TS    128
#define NBLK  (NROWS / TS)   // 64 column-blocks in similarity partials
#define LDAB  80             // smem row stride (bytes): 32 bf16 + 16B pad

// ---------------- device scratch (no allocations allowed) ----------------
__device__ __nv_bfloat16 g_Zh[NROWS * DDIM];
__device__ __nv_bfloat16 g_Zl[NROWS * DDIM];
__device__ __nv_bfloat16 g_Th[NROWS * DDIM];
__device__ __nv_bfloat16 g_Tl[NROWS * DDIM];
__device__ __nv_bfloat16 g_W1h[DDIM * DDIM];
__device__ __nv_bfloat16 g_W1l[DDIM * DDIM];
__device__ __nv_bfloat16 g_W2h[DDIM * DDIM];
__device__ __nv_bfloat16 g_W2l[DDIM * DDIM];
__device__ float g_H [NROWS * DDIM];
__device__ float g_N1[NROWS * DDIM];
__device__ float g_N2[NROWS * DDIM];
__device__ __nv_bfloat16 g_B1[NROWS * DDIM];
__device__ __nv_bfloat16 g_B2[NROWS * DDIM];
__device__ float g_rs11p[NROWS * NBLK];
__device__ float g_rs22p[NROWS * NBLK];
__device__ float g_rs12p[NROWS * NBLK];
__device__ float g_cs12p[NROWS * NBLK];
__device__ float g_d12 [NROWS];
__device__ float g_loss[NROWS];

// ====================== helpers ======================
__device__ __forceinline__ uint32_t smem_u32(const void* p) {
    uint32_t a;
    asm("{ .reg .u64 t; cvta.to.shared.u64 t, %1; cvt.u32.u64 %0, t; }"
        : "=r"(a) : "l"(p));
    return a;
}
__device__ __forceinline__ void ldsm_x4(uint32_t (&r)[4], uint32_t addr) {
    asm volatile("ldmatrix.sync.aligned.m8n8.x4.shared.b16 {%0,%1,%2,%3}, [%4];"
        : "=r"(r[0]), "=r"(r[1]), "=r"(r[2]), "=r"(r[3]) : "r"(addr));
}
__device__ __forceinline__ void mma16816(float (&d)[4], const uint32_t (&a)[4],
                                         uint32_t b0, uint32_t b1) {
    asm volatile("mma.sync.aligned.m16n8k16.row.col.f32.bf16.bf16.f32 "
        "{%0,%1,%2,%3}, {%4,%5,%6,%7}, {%8,%9}, {%0,%1,%2,%3};"
        : "+f"(d[0]), "+f"(d[1]), "+f"(d[2]), "+f"(d[3])
        : "r"(a[0]), "r"(a[1]), "r"(a[2]), "r"(a[3]), "r"(b0), "r"(b1));
}
__device__ __forceinline__ float fast_exp2(float x) {
    float y; asm("ex2.approx.f32 %0, %1;" : "=f"(y) : "f"(x)); return y;
}
__device__ __forceinline__ void split2(float x, __nv_bfloat16& h, __nv_bfloat16& l) {
    h = __float2bfloat16(x);
    l = __float2bfloat16(x - __bfloat162float(h));
}

// ================== split kernel: fp32 -> (hi, lo) bf16 ==================
__global__ void __launch_bounds__(256)
split_kernel(const float* __restrict__ X, __nv_bfloat16* __restrict__ Hi,
             __nv_bfloat16* __restrict__ Lo) {
    const int i = (blockIdx.x * 256 + threadIdx.x) * 4;
    float4 v = *(const float4*)(X + i);
    __nv_bfloat16 h0, h1, h2, h3, l0, l1, l2, l3;
    split2(v.x, h0, l0); split2(v.y, h1, l1);
    split2(v.z, h2, l2); split2(v.w, h3, l3);
    __nv_bfloat162 hp0 = {h0, h1}, hp1 = {h2, h3};
    __nv_bfloat162 lp0 = {l0, l1}, lp1 = {l2, l3};
    *(uint2*)(Hi + i) = make_uint2(*(uint32_t*)&hp0, *(uint32_t*)&hp1);
    *(uint2*)(Lo + i) = make_uint2(*(uint32_t*)&lp0, *(uint32_t*)&lp1);
}

// ================== split-bf16 projection GEMM ==================
// OUT[128x128 tile] = act( A(rb rows) · W(cb rows)^T + bias ), near-fp32 via
// hi*hi + hi*lo + lo*hi.  A: [8192,512], W: [512,512], both row-major bf16 pairs.
template <bool DO_ELU, bool SPLIT_OUT>
__global__ void __launch_bounds__(256, 2)
proj_mma_kernel(const __nv_bfloat16* __restrict__ Ah, const __nv_bfloat16* __restrict__ Al,
                const __nv_bfloat16* __restrict__ Wh, const __nv_bfloat16* __restrict__ Wl,
                const float* __restrict__ bias,
                float* __restrict__ Hout,
                __nv_bfloat16* __restrict__ Oh, __nv_bfloat16* __restrict__ Ol) {
    __shared__ __align__(128) char sm[4 * 128 * LDAB];
    const uint32_t s0 = smem_u32(sm);
    const uint32_t sAh = s0, sAl = s0 + 128 * LDAB,
                   sWh = s0 + 2 * 128 * LDAB, sWl = s0 + 3 * 128 * LDAB;

    const int tid = threadIdx.x, lane = tid & 31, wid = tid >> 5;
    const int warp_m = wid & 3, warp_n = wid >> 2;
    const int cb = blockIdx.x, rb = blockIdx.y;

    const char* Agh = (const char*)(Ah + (size_t)rb * TS * DDIM);
    const char* Agl = (const char*)(Al + (size_t)rb * TS * DDIM);
    const char* Wgh = (const char*)(Wh + (size_t)cb * TS * DDIM);
    const char* Wgl = (const char*)(Wl + (size_t)cb * TS * DDIM);

    const int r0 = tid >> 2, p0 = tid & 3;
    const int q = lane >> 3, rr = lane & 7;
    const uint32_t lds_off = (uint32_t)(((q & 1) * 8 + rr) * LDAB + (q >> 1) * 16);
    const uint32_t ah_base = sAh + (uint32_t)(warp_m * 32) * LDAB + lds_off;
    const uint32_t al_base = sAl + (uint32_t)(warp_m * 32) * LDAB + lds_off;
    const uint32_t bh_base = sWh + (uint32_t)(warp_n * 64) * LDAB + lds_off;
    const uint32_t bl_base = sWl + (uint32_t)(warp_n * 64) * LDAB + lds_off;

    float acc[2][8][4] = {};

    for (int kc = 0; kc < 16; kc++) {
        __syncthreads();
        {
            const size_t g0 = (size_t)r0 * (DDIM * 2) + (size_t)kc * 64 + p0 * 16;
            const size_t g1 = g0 + (size_t)64 * (DDIM * 2);
            const uint32_t so0 = (uint32_t)(r0 * LDAB + p0 * 16);
            const uint32_t so1 = so0 + 64 * LDAB;
            uint4 a0 = *(const uint4*)(Agh + g0), a1 = *(const uint4*)(Agh + g1);
            uint4 b0 = *(const uint4*)(Agl + g0), b1 = *(const uint4*)(Agl + g1);
            uint4 c0 = *(const uint4*)(Wgh + g0), c1 = *(const uint4*)(Wgh + g1);
            uint4 d0 = *(const uint4*)(Wgl + g0), d1 = *(const uint4*)(Wgl + g1);
            *(uint4*)(sm + so0)                  = a0;
            *(uint4*)(sm + so1)                  = a1;
            *(uint4*)(sm + 128 * LDAB + so0)     = b0;
            *(uint4*)(sm + 128 * LDAB + so1)     = b1;
            *(uint4*)(sm + 2 * 128 * LDAB + so0) = c0;
            *(uint4*)(sm + 2 * 128 * LDAB + so1) = c1;
            *(uint4*)(sm + 3 * 128 * LDAB + so0) = d0;
            *(uint4*)(sm + 3 * 128 * LDAB + so1) = d1;
        }
        __syncthreads();

#pragma unroll
        for (int kk = 0; kk < 2; kk++) {
            uint32_t ah[2][4], al[2][4];
            ldsm_x4(ah[0], ah_base + kk * 32);
            ldsm_x4(ah[1], ah_base + 16 * LDAB + kk * 32);
            ldsm_x4(al[0], al_base + kk * 32);
            ldsm_x4(al[1], al_base + 16 * LDAB + kk * 32);
#pragma unroll
            for (int n2 = 0; n2 < 4; n2++) {
                uint32_t bh[4], bl[4];
                ldsm_x4(bh, bh_base + n2 * 16 * LDAB + kk * 32);
                ldsm_x4(bl, bl_base + n2 * 16 * LDAB + kk * 32);
#pragma unroll
                for (int mt = 0; mt < 2; mt++)
#pragma unroll
                    for (int u = 0; u < 2; u++) {
                        const int nt = n2 * 2 + u;
                        mma16816(acc[mt][nt], ah[mt], bh[u], bh[u + 2]);
                        mma16816(acc[mt][nt], ah[mt], bl[u], bl[u + 2]);
                        mma16816(acc[mt][nt], al[mt], bh[u], bh[u + 2]);
                    }
            }
        }
    }

    // ---- epilogue: bias (+ELU), store fp32 or split-bf16 ----
    const int cbase = cb * TS + warp_n * 64;
    const int rbase = rb * TS + warp_m * 32 + (lane >> 2);
#pragma unroll
    for (int mt = 0; mt < 2; mt++) {
        const int ra = rbase + mt * 16, rbb = ra + 8;
#pragma unroll
        for (int nt = 0; nt < 8; nt++) {
            const int c = cbase + nt * 8 + (lane & 3) * 2;
            const float bv0 = bias[c], bv1 = bias[c + 1];
            float x00 = acc[mt][nt][0] + bv0, x01 = acc[mt][nt][1] + bv1;
            float x10 = acc[mt][nt][2] + bv0, x11 = acc[mt][nt][3] + bv1;
            if (DO_ELU) {
                x00 = (x00 > 0.0f) ? x00 : expm1f(x00);
                x01 = (x01 > 0.0f) ? x01 : expm1f(x01);
                x10 = (x10 > 0.0f) ? x10 : expm1f(x10);
                x11 = (x11 > 0.0f) ? x11 : expm1f(x11);
            }
            if (SPLIT_OUT) {
                __nv_bfloat16 h0, h1, l0, l1;
                split2(x00, h0, l0); split2(x01, h1, l1);
                __nv_bfloat162 hp = {h0, h1}, lp = {l0, l1};
                *(uint32_t*)(Oh + (size_t)ra * DDIM + c) = *(uint32_t*)&hp;
                *(uint32_t*)(Ol + (size_t)ra * DDIM + c) = *(uint32_t*)&lp;
                split2(x10, h0, l0); split2(x11, h1, l1);
                __nv_bfloat162 hq = {h0, h1}, lq = {l0, l1};
                *(uint32_t*)(Oh + (size_t)rbb * DDIM + c) = *(uint32_t*)&hq;
                *(uint32_t*)(Ol + (size_t)rbb * DDIM + c) = *(uint32_t*)&lq;
            } else {
                *(float2*)(Hout + (size_t)ra  * DDIM + c) = make_float2(x00, x01);
                *(float2*)(Hout + (size_t)rbb * DDIM + c) = make_float2(x10, x11);
            }
        }
    }
}

// ================= similarity tile core (mma.sync bf16) =================
// Computes acc = A_tile(128) · B_tile(128)^T over K=512 for one 128x128 tile.
__device__ __forceinline__ void sim_tile_mma(const char* Ag, const char* Bg,
                                             char* sm, uint32_t sA, uint32_t sB,
                                             float (&acc)[2][8][4],
                                             int tid, int lane, int warp_m, int warp_n) {
    const int r0 = tid >> 2, p0 = tid & 3;
    const int q = lane >> 3, rr = lane & 7;
    const uint32_t lds_off = (uint32_t)(((q & 1) * 8 + rr) * LDAB + (q >> 1) * 16);
    const uint32_t a_base = sA + (uint32_t)(warp_m * 32) * LDAB + lds_off;
    const uint32_t b_base = sB + (uint32_t)(warp_n * 64) * LDAB + lds_off;

    for (int kc = 0; kc < 16; kc++) {
        __syncthreads();
        {
            const size_t g0 = (size_t)r0 * (DDIM * 2) + (size_t)kc * 64 + p0 * 16;
            const size_t g1 = g0 + (size_t)64 * (DDIM * 2);
            uint4 va0 = *(const uint4*)(Ag + g0);
            uint4 va1 = *(const uint4*)(Ag + g1);
            uint4 vb0 = *(const uint4*)(Bg + g0);
            uint4 vb1 = *(const uint4*)(Bg + g1);
            const uint32_t so0 = (uint32_t)(r0 * LDAB + p0 * 16);
            const uint32_t so1 = so0 + 64 * LDAB;
            *(uint4*)(sm + so0)              = va0;
            *(uint4*)(sm + so1)              = va1;
            *(uint4*)(sm + 128 * LDAB + so0) = vb0;
            *(uint4*)(sm + 128 * LDAB + so1) = vb1;
        }
        __syncthreads();

#pragma unroll
        for (int kk = 0; kk < 2; kk++) {
            uint32_t af[2][4];
            ldsm_x4(af[0], a_base + kk * 32);
            ldsm_x4(af[1], a_base + 16 * LDAB + kk * 32);
#pragma unroll
            for (int n2 = 0; n2 < 4; n2++) {
                uint32_t bf[4];
                ldsm_x4(bf, b_base + n2 * 16 * LDAB + kk * 32);
#pragma unroll
                for (int mt = 0; mt < 2; mt++)
#pragma unroll
                    for (int u = 0; u < 2; u++)
                        mma16816(acc[mt][n2 * 2 + u], af[mt], bf[u], bf[u + 2]);
            }
        }
    }
    __syncthreads();   // smem reusable after this
}

// exp + row/col reductions shared by both sim kernels.
// rs_sm: [128][2] (row sums per warp_n half), cs_sm: [4][128] (col sums per warp_m)
__device__ __forceinline__ void sim_reduce(float (&acc)[2][8][4], char* sm,
                                           int lane, int warp_m, int warp_n,
                                           bool do_col) {
    float* rs_sm = (float*)sm;
    float* cs_sm = (float*)(sm + 1024);
    const float C = 2.8853900817779268f;  // 2 / ln2
    float rs_acc[2][2] = {};
    float cs2[8][2];
    if (do_col)
#pragma unroll
        for (int nt = 0; nt < 8; nt++) cs2[nt][0] = cs2[nt][1] = 0.0f;

#pragma unroll
    for (int mt = 0; mt < 2; mt++)
#pragma unroll
        for (int nt = 0; nt < 8; nt++) {
            float e0 = fast_exp2(acc[mt][nt][0] * C);
            float e1 = fast_exp2(acc[mt][nt][1] * C);
            float e2 = fast_exp2(acc[mt][nt][2] * C);
            float e3 = fast_exp2(acc[mt][nt][3] * C);
            rs_acc[mt][0] += e0 + e1;
            rs_acc[mt][1] += e2 + e3;
            if (do_col) { cs2[nt][0] += e0 + e2; cs2[nt][1] += e1 + e3; }
        }

#pragma unroll
    for (int mt = 0; mt < 2; mt++)
#pragma unroll
        for (int half = 0; half < 2; half++) {
            float v = rs_acc[mt][half];
            v += __shfl_xor_sync(0xffffffffu, v, 1);
            v += __shfl_xor_sync(0xffffffffu, v, 2);
            if ((lane & 3) == 0) {
                int row = warp_m * 32 + mt * 16 + half * 8 + (lane >> 2);
                rs_sm[row * 2 + warp_n] = v;
            }
        }
    if (do_col) {
#pragma unroll
        for (int nt = 0; nt < 8; nt++)
#pragma unroll
            for (int e = 0; e < 2; e++) {
                float v = cs2[nt][e];
                v += __shfl_xor_sync(0xffffffffu, v, 4);
                v += __shfl_xor_sync(0xffffffffu, v, 8);
                v += __shfl_xor_sync(0xffffffffu, v, 16);
                if (lane < 4) {
                    int col = warp_n * 64 + nt * 8 + lane * 2 + e;
                    cs_sm[warp_m * 128 + col] = v;
                }
            }
    }
    __syncthreads();
}

// S12 kernel: all tiles; rowsums -> rspart, colsums -> cspart
__global__ void __launch_bounds__(256, 2)
sim12_kernel(const __nv_bfloat16* __restrict__ A, const __nv_bfloat16* __restrict__ B,
             float* __restrict__ rspart, float* __restrict__ cspart) {
    __shared__ __align__(128) char sm[2 * 128 * LDAB];
    const uint32_t sA = smem_u32(sm), sB = sA + 128 * LDAB;
    const int tid = threadIdx.x, lane = tid & 31, wid = tid >> 5;
    const int warp_m = wid & 3, warp_n = wid >> 2;
    const int rb = blockIdx.y, cb = blockIdx.x;

    float acc[2][8][4] = {};
    sim_tile_mma((const char*)(A + (size_t)rb * TS * DDIM),
                 (const char*)(B + (size_t)cb * TS * DDIM),
                 sm, sA, sB, acc, tid, lane, warp_m, warp_n);
    sim_reduce(acc, sm, lane, warp_m, warp_n, true);

    float* rs_sm = (float*)sm;
    float* cs_sm = (float*)(sm + 1024);
    if (tid < TS) {
        rspart[(size_t)(rb * TS + tid) * NBLK + cb] = rs_sm[tid * 2] + rs_sm[tid * 2 + 1];
        cspart[(size_t)(cb * TS + tid) * NBLK + rb] =
            cs_sm[tid] + cs_sm[128 + tid] + cs_sm[256 + tid] + cs_sm[384 + tid];
    }
}

// Symmetric kernel (S11/S22): only tiles cb >= rb; colsums fill the mirror slots.
__global__ void __launch_bounds__(256, 2)
simsym_kernel(const __nv_bfloat16* __restrict__ A, float* __restrict__ rspart) {
    const int rb = blockIdx.y, cb = blockIdx.x;
    if (cb < rb) return;
    __shared__ __align__(128) char sm[2 * 128 * LDAB];
    const uint32_t sA = smem_u32(sm), sB = sA + 128 * LDAB;
    const int tid = threadIdx.x, lane = tid & 31, wid = tid >> 5;
    const int warp_m = wid & 3, warp_n = wid >> 2;
    const bool diag = (cb == rb);

    float acc[2][8][4] = {};
    sim_tile_mma((const char*)(A + (size_t)rb * TS * DDIM),
                 (const char*)(A + (size_t)cb * TS * DDIM),
                 sm, sA, sB, acc, tid, lane, warp_m, warp_n);
    sim_reduce(acc, sm, lane, warp_m, warp_n, !diag);

    float* rs_sm = (float*)sm;
    float* cs_sm = (float*)(sm + 1024);
    if (tid < TS) {
        rspart[(size_t)(rb * TS + tid) * NBLK + cb] = rs_sm[tid * 2] + rs_sm[tid * 2 + 1];
        if (!diag)
            rspart[(size_t)(cb * TS + tid) * NBLK + rb] =
                cs_sm[tid] + cs_sm[128 + tid] + cs_sm[256 + tid] + cs_sm[384 + tid];
    }
}

// ---------------- row L2-normalize -> fp32 + bf16 outputs -----------------
__global__ void __launch_bounds__(256)
normalize_kernel(const float* __restrict__ H, float* __restrict__ O,
                 __nv_bfloat16* __restrict__ Ob) {
    const int row  = blockIdx.x * 8 + (threadIdx.x >> 5);
    const int lane = threadIdx.x & 31;
    const float4* hp = (const float4*)(H + (size_t)row * DDIM);
    float4* op = (float4*)(O + (size_t)row * DDIM);
    float4 v[4];
    float ss = 0.0f;
#pragma unroll
    for (int m = 0; m < 4; m++) {
        v[m] = hp[lane + 32 * m];
        ss += v[m].x * v[m].x + v[m].y * v[m].y + v[m].z * v[m].z + v[m].w * v[m].w;
    }
#pragma unroll
    for (int o = 16; o > 0; o >>= 1) ss += __shfl_xor_sync(0xffffffffu, ss, o);
    const float inv = 1.0f / fmaxf(sqrtf(ss), 1e-12f);
#pragma unroll
    for (int m = 0; m < 4; m++) {
        float4 w = v[m];
        w.x *= inv; w.y *= inv; w.z *= inv; w.w *= inv;
        op[lane + 32 * m] = w;
        __nv_bfloat162 p0 = __floats2bfloat162_rn(w.x, w.y);
        __nv_bfloat162 p1 = __floats2bfloat162_rn(w.z, w.w);
        *(uint2*)(Ob + (size_t)row * DDIM + (lane + 32 * m) * 4) =
            make_uint2(*(uint32_t*)&p0, *(uint32_t*)&p1);
    }
}

__global__ void __launch_bounds__(256)
d12_kernel(const float* __restrict__ N1, const float* __restrict__ N2,
           float* __restrict__ d12) {
    const int row  = blockIdx.x * 8 + (threadIdx.x >> 5);
    const int lane = threadIdx.x & 31;
    const float4* a = (const float4*)(N1 + (size_t)row * DDIM);
    const float4* b = (const float4*)(N2 + (size_t)row * DDIM);
    float s = 0.0f;
#pragma unroll
    for (int m = 0; m < 4; m++) {
        float4 x = a[lane + 32 * m], y = b[lane + 32 * m];
        s += x.x * y.x + x.y * y.y + x.z * y.z + x.w * y.w;
    }
#pragma unroll
    for (int o = 16; o > 0; o >>= 1) s += __shfl_xor_sync(0xffffffffu, s, o);
    if (lane == 0) d12[row] = s;
}

__global__ void __launch_bounds__(256)
rowloss_kernel(const float* __restrict__ rs11p, const float* __restrict__ rs22p,
               const float* __restrict__ rs12p, const float* __restrict__ cs12p,
               const float* __restrict__ d12, float* __restrict__ loss) {
    const int row  = blockIdx.x * 8 + (threadIdx.x >> 5);
    const int lane = threadIdx.x & 31;
    float s11 = 0.0f, s22 = 0.0f, s12 = 0.0f, c12 = 0.0f;
    for (int m = lane; m < NBLK; m += 32) {
        const size_t o = (size_t)row * NBLK + m;
        s11 += rs11p[o];
        s22 += rs22p[o];
        s12 += rs12p[o];
        c12 += cs12p[o];
    }
#pragma unroll
    for (int o = 16; o > 0; o >>= 1) {
        s11 += __shfl_xor_sync(0xffffffffu, s11, o);
        s22 += __shfl_xor_sync(0xffffffffu, s22, o);
        s12 += __shfl_xor_sync(0xffffffffu, s12, o);
        c12 += __shfl_xor_sync(0xffffffffu, c12, o);
    }
    if (lane == 0) {
        const float E2 = 7.38905609893065f;   // exp(1/tau)
        const float den1 = s11 + s12 - E2;
        const float den2 = s22 + c12 - E2;
        loss[row] = -2.0f * d12[row] + 0.5f * (__logf(den1) + __logf(den2));
    }
}

__global__ void __launch_bounds__(1024)
final_kernel(const float* __restrict__ loss, float* __restrict__ out) {
    __shared__ float sm[1024];
    const int t = threadIdx.x;
    float s = 0.0f;
    for (int i = t; i < NROWS; i += 1024) s += loss[i];
    sm[t] = s;
    __syncthreads();
    for (int o = 512; o > 0; o >>= 1) {
        if (t < o) sm[t] += sm[t + o];
        __syncthreads();
    }
    if (t == 0) out[0] = sm[0] * (1.0f / NROWS);
}

// ---------------- launch ----------------------------------------------------
extern "C" void kernel_launch(void* const* d_in, const int* in_sizes, int n_in,
                              void* d_out, int out_size) {
    const float* pri = (const float*)d_in[0];
    const float* aux = (const float*)d_in[1];
    const float* W1  = (const float*)d_in[2];
    const float* b1  = (const float*)d_in[3];
    const float* W2  = (const float*)d_in[4];
    const float* b2  = (const float*)d_in[5];
    float* out = (float*)d_out;

    __nv_bfloat16 *Zh, *Zl, *Th, *Tl, *W1h, *W1l, *W2h, *W2l, *B1, *B2;
    float *H, *N1, *N2, *rs11p, *rs22p, *rs12p, *cs12p, *d12, *loss;
    cudaGetSymbolAddress((void**)&Zh,  g_Zh);
    cudaGetSymbolAddress((void**)&Zl,  g_Zl);
    cudaGetSymbolAddress((void**)&Th,  g_Th);
    cudaGetSymbolAddress((void**)&Tl,  g_Tl);
    cudaGetSymbolAddress((void**)&W1h, g_W1h);
    cudaGetSymbolAddress((void**)&W1l, g_W1l);
    cudaGetSymbolAddress((void**)&W2h, g_W2h);
    cudaGetSymbolAddress((void**)&W2l, g_W2l);
    cudaGetSymbolAddress((void**)&H,   g_H);
    cudaGetSymbolAddress((void**)&N1,  g_N1);
    cudaGetSymbolAddress((void**)&N2,  g_N2);
    cudaGetSymbolAddress((void**)&B1,  g_B1);
    cudaGetSymbolAddress((void**)&B2,  g_B2);
    cudaGetSymbolAddress((void**)&rs11p, g_rs11p);
    cudaGetSymbolAddress((void**)&rs22p, g_rs22p);
    cudaGetSymbolAddress((void**)&rs12p, g_rs12p);
    cudaGetSymbolAddress((void**)&cs12p, g_cs12p);
    cudaGetSymbolAddress((void**)&d12,  g_d12);
    cudaGetSymbolAddress((void**)&loss, g_loss);

    const dim3 pg(DDIM / TS, NROWS / TS);   // (4, 64)
    const dim3 sg(NBLK, NBLK);              // (64, 64)
    const int nW = DDIM * DDIM / 1024;      // 256 blocks
    const int nZ = NROWS * DDIM / 1024;     // 4096 blocks

    split_kernel<<<nW, 256>>>(W1, W1h, W1l);
    split_kernel<<<nW, 256>>>(W2, W2h, W2l);

    // pri -> N1/B1
    split_kernel<<<nZ, 256>>>(pri, Zh, Zl);
    proj_mma_kernel<true,  true ><<<pg, 256>>>(Zh, Zl, W1h, W1l, b1, nullptr, Th, Tl);
    proj_mma_kernel<false, false><<<pg, 256>>>(Th, Tl, W2h, W2l, b2, H, nullptr, nullptr);
    normalize_kernel<<<NROWS / 8, 256>>>(H, N1, B1);
    // aux -> N2/B2
    split_kernel<<<nZ, 256>>>(aux, Zh, Zl);
    proj_mma_kernel<true,  true ><<<pg, 256>>>(Zh, Zl, W1h, W1l, b1, nullptr, Th, Tl);
    proj_mma_kernel<false, false><<<pg, 256>>>(Th, Tl, W2h, W2l, b2, H, nullptr, nullptr);
    normalize_kernel<<<NROWS / 8, 256>>>(H, N2, B2);

    d12_kernel<<<NROWS / 8, 256>>>(N1, N2, d12);

    simsym_kernel<<<sg, 256>>>(B1, rs11p);
    simsym_kernel<<<sg, 256>>>(B2, rs22p);
    sim12_kernel <<<sg, 256>>>(B1, B2, rs12p, cs12p);

    rowloss_kernel<<<NROWS / 8, 256>>>(rs11p, rs22p, rs12p, cs12p, d12, loss);
    final_kernel<<<1, 1024>>>(loss, out);
}

// round 5
// speedup vs baseline: 6.9667x; 1.0377x over previous
#include <cuda_runtime.h>
#include <cuda_bf16.h>
#include <math.h>
#include <stdint.h>

#define NROWS 8192
#define DDIM  512
#define TS    128
#define NBLK  (NROWS / TS)   // 64
#define LDAB  80             // smem row stride (bytes): 32 bf16 + 16B pad
#define SIMSTG (2 * 128 * LDAB)   // 20480 per sim stage
#define PROJSTG (4 * 128 * LDAB)  // 40960 per proj stage
#define NSYM  (NBLK * (NBLK + 1) / 2)   // 2080

// ---------------- device scratch ----------------
__device__ __nv_bfloat16 g_Zh[NROWS * DDIM];
__device__ __nv_bfloat16 g_Zl[NROWS * DDIM];
__device__ __nv_bfloat16 g_Th[NROWS * DDIM];
__device__ __nv_bfloat16 g_Tl[NROWS * DDIM];
__device__ __nv_bfloat16 g_W1h[DDIM * DDIM];
__device__ __nv_bfloat16 g_W1l[DDIM * DDIM];
__device__ __nv_bfloat16 g_W2h[DDIM * DDIM];
__device__ __nv_bfloat16 g_W2l[DDIM * DDIM];
__device__ float g_H [NROWS * DDIM];
__device__ float g_N1[NROWS * DDIM];
__device__ float g_N2[NROWS * DDIM];
__device__ __nv_bfloat16 g_B1[NROWS * DDIM];
__device__ __nv_bfloat16 g_B2[NROWS * DDIM];
__device__ float g_rs11p[NROWS * NBLK];
__device__ float g_rs22p[NROWS * NBLK];
__device__ float g_rs12p[NROWS * NBLK];
__device__ float g_cs12p[NROWS * NBLK];
__device__ float g_d12 [NROWS];
__device__ float g_loss[NROWS];

// ====================== helpers ======================
__device__ __forceinline__ uint32_t smem_u32(const void* p) {
    uint32_t a;
    asm("{ .reg .u64 t; cvta.to.shared.u64 t, %1; cvt.u32.u64 %0, t; }"
        : "=r"(a) : "l"(p));
    return a;
}
__device__ __forceinline__ void ldsm_x4(uint32_t (&r)[4], uint32_t addr) {
    asm volatile("ldmatrix.sync.aligned.m8n8.x4.shared.b16 {%0,%1,%2,%3}, [%4];"
        : "=r"(r[0]), "=r"(r[1]), "=r"(r[2]), "=r"(r[3]) : "r"(addr));
}
__device__ __forceinline__ void mma16816(float (&d)[4], const uint32_t (&a)[4],
                                         uint32_t b0, uint32_t b1) {
    asm volatile("mma.sync.aligned.m16n8k16.row.col.f32.bf16.bf16.f32 "
        "{%0,%1,%2,%3}, {%4,%5,%6,%7}, {%8,%9}, {%0,%1,%2,%3};"
        : "+f"(d[0]), "+f"(d[1]), "+f"(d[2]), "+f"(d[3])
        : "r"(a[0]), "r"(a[1]), "r"(a[2]), "r"(a[3]), "r"(b0), "r"(b1));
}
#define CP16(dst, src) \
    asm volatile("cp.async.cg.shared.global [%0], [%1], 16;" :: "r"(dst), "l"(src))
#define CPCOMMIT() asm volatile("cp.async.commit_group;" ::: "memory")
#define CPWAIT(n)  asm volatile("cp.async.wait_group %0;" :: "n"(n) : "memory")

__device__ __forceinline__ float fast_exp2(float x) {
    float y; asm("ex2.approx.f32 %0, %1;" : "=f"(y) : "f"(x)); return y;
}
__device__ __forceinline__ void split2(float x, __nv_bfloat16& h, __nv_bfloat16& l) {
    h = __float2bfloat16(x);
    l = __float2bfloat16(x - __bfloat162float(h));
}

// ================== split kernel: fp32 -> (hi, lo) bf16 ==================
__global__ void __launch_bounds__(256)
split_kernel(const float* __restrict__ X, __nv_bfloat16* __restrict__ Hi,
             __nv_bfloat16* __restrict__ Lo) {
    const int i = (blockIdx.x * 256 + threadIdx.x) * 4;
    float4 v = *(const float4*)(X + i);
    __nv_bfloat16 h0, h1, h2, h3, l0, l1, l2, l3;
    split2(v.x, h0, l0); split2(v.y, h1, l1);
    split2(v.z, h2, l2); split2(v.w, h3, l3);
    __nv_bfloat162 hp0 = {h0, h1}, hp1 = {h2, h3};
    __nv_bfloat162 lp0 = {l0, l1}, lp1 = {l2, l3};
    *(uint2*)(Hi + i) = make_uint2(*(uint32_t*)&hp0, *(uint32_t*)&hp1);
    *(uint2*)(Lo + i) = make_uint2(*(uint32_t*)&lp0, *(uint32_t*)&lp1);
}

// ================== split-bf16 projection GEMM (2-stage cp.async) ==========
template <bool DO_ELU, bool SPLIT_OUT>
__global__ void __launch_bounds__(256)
proj_mma_kernel(const __nv_bfloat16* __restrict__ Ah, const __nv_bfloat16* __restrict__ Al,
                const __nv_bfloat16* __restrict__ Wh, const __nv_bfloat16* __restrict__ Wl,
                const float* __restrict__ bias,
                float* __restrict__ Hout,
                __nv_bfloat16* __restrict__ Oh, __nv_bfloat16* __restrict__ Ol) {
    extern __shared__ __align__(128) char dynsm[];
    const uint32_t s0 = smem_u32(dynsm);

    const int tid = threadIdx.x, lane = tid & 31, wid = tid >> 5;
    const int warp_m = wid & 3, warp_n = wid >> 2;
    const int cb = blockIdx.x, rb = blockIdx.y;

    const char* Agh = (const char*)(Ah + (size_t)rb * TS * DDIM);
    const char* Agl = (const char*)(Al + (size_t)rb * TS * DDIM);
    const char* Wgh = (const char*)(Wh + (size_t)cb * TS * DDIM);
    const char* Wgl = (const char*)(Wl + (size_t)cb * TS * DDIM);

    const int r0 = tid >> 2, p0 = tid & 3;
    const uint32_t so0 = (uint32_t)(r0 * LDAB + p0 * 16);
    const uint32_t so1 = so0 + 64 * LDAB;

    const int q = lane >> 3, rr = lane & 7;
    const uint32_t lds_off = (uint32_t)(((q & 1) * 8 + rr) * LDAB + (q >> 1) * 16);
    const uint32_t am_off = (uint32_t)(warp_m * 32) * LDAB + lds_off;
    const uint32_t wn_off = (uint32_t)(warp_n * 64) * LDAB + lds_off;

    float acc[2][8][4] = {};

    auto load_chunk = [&](int kc, int stg) {
        const size_t g0 = (size_t)r0 * (DDIM * 2) + (size_t)kc * 64 + p0 * 16;
        const size_t g1 = g0 + (size_t)64 * (DDIM * 2);
        const uint32_t b = s0 + stg * PROJSTG;
        CP16(b + so0,                  Agh + g0);
        CP16(b + so1,                  Agh + g1);
        CP16(b + 128 * LDAB + so0,     Agl + g0);
        CP16(b + 128 * LDAB + so1,     Agl + g1);
        CP16(b + 2 * 128 * LDAB + so0, Wgh + g0);
        CP16(b + 2 * 128 * LDAB + so1, Wgh + g1);
        CP16(b + 3 * 128 * LDAB + so0, Wgl + g0);
        CP16(b + 3 * 128 * LDAB + so1, Wgl + g1);
        CPCOMMIT();
    };

    load_chunk(0, 0);
    for (int kc = 0; kc < 16; kc++) {
        if (kc + 1 < 16) load_chunk(kc + 1, (kc + 1) & 1);
        if (kc < 15) { CPWAIT(1); } else { CPWAIT(0); }
        __syncthreads();
        const uint32_t b = s0 + (kc & 1) * PROJSTG;
        const uint32_t ah_base = b + am_off;
        const uint32_t al_base = b + 128 * LDAB + am_off;
        const uint32_t bh_base = b + 2 * 128 * LDAB + wn_off;
        const uint32_t bl_base = b + 3 * 128 * LDAB + wn_off;
#pragma unroll
        for (int kk = 0; kk < 2; kk++) {
            uint32_t ah[2][4], al[2][4];
            ldsm_x4(ah[0], ah_base + kk * 32);
            ldsm_x4(ah[1], ah_base + 16 * LDAB + kk * 32);
            ldsm_x4(al[0], al_base + kk * 32);
            ldsm_x4(al[1], al_base + 16 * LDAB + kk * 32);
#pragma unroll
            for (int n2 = 0; n2 < 4; n2++) {
                uint32_t bh[4], bl[4];
                ldsm_x4(bh, bh_base + n2 * 16 * LDAB + kk * 32);
                ldsm_x4(bl, bl_base + n2 * 16 * LDAB + kk * 32);
#pragma unroll
                for (int mt = 0; mt < 2; mt++)
#pragma unroll
                    for (int u = 0; u < 2; u++) {
                        const int nt = n2 * 2 + u;
                        mma16816(acc[mt][nt], ah[mt], bh[u], bh[u + 2]);
                        mma16816(acc[mt][nt], ah[mt], bl[u], bl[u + 2]);
                        mma16816(acc[mt][nt], al[mt], bh[u], bh[u + 2]);
                    }
            }
        }
        __syncthreads();
    }

    // ---- epilogue: bias (+ELU), store fp32 or split-bf16 ----
    const int cbase = cb * TS + warp_n * 64;
    const int rbase = rb * TS + warp_m * 32 + (lane >> 2);
#pragma unroll
    for (int mt = 0; mt < 2; mt++) {
        const int ra = rbase + mt * 16, rbb = ra + 8;
#pragma unroll
        for (int nt = 0; nt < 8; nt++) {
            const int c = cbase + nt * 8 + (lane & 3) * 2;
            const float bv0 = bias[c], bv1 = bias[c + 1];
            float x00 = acc[mt][nt][0] + bv0, x01 = acc[mt][nt][1] + bv1;
            float x10 = acc[mt][nt][2] + bv0, x11 = acc[mt][nt][3] + bv1;
            if (DO_ELU) {
                x00 = (x00 > 0.0f) ? x00 : expm1f(x00);
                x01 = (x01 > 0.0f) ? x01 : expm1f(x01);
                x10 = (x10 > 0.0f) ? x10 : expm1f(x10);
                x11 = (x11 > 0.0f) ? x11 : expm1f(x11);
            }
            if (SPLIT_OUT) {
                __nv_bfloat16 h0, h1, l0, l1;
                split2(x00, h0, l0); split2(x01, h1, l1);
                __nv_bfloat162 hp = {h0, h1}, lp = {l0, l1};
                *(uint32_t*)(Oh + (size_t)ra * DDIM + c) = *(uint32_t*)&hp;
                *(uint32_t*)(Ol + (size_t)ra * DDIM + c) = *(uint32_t*)&lp;
                split2(x10, h0, l0); split2(x11, h1, l1);
                __nv_bfloat162 hq = {h0, h1}, lq = {l0, l1};
                *(uint32_t*)(Oh + (size_t)rbb * DDIM + c) = *(uint32_t*)&hq;
                *(uint32_t*)(Ol + (size_t)rbb * DDIM + c) = *(uint32_t*)&lq;
            } else {
                *(float2*)(Hout + (size_t)ra  * DDIM + c) = make_float2(x00, x01);
                *(float2*)(Hout + (size_t)rbb * DDIM + c) = make_float2(x10, x11);
            }
        }
    }
}

// ================= similarity tile core (3-stage cp.async) =================
__device__ __forceinline__ void sim_tile_mma(const char* Ag, const char* Bg,
                                             uint32_t s0,
                                             float (&acc)[2][8][4],
                                             int tid, int lane, int warp_m, int warp_n) {
    const int r0 = tid >> 2, p0 = tid & 3;
    const uint32_t so0 = (uint32_t)(r0 * LDAB + p0 * 16);
    const uint32_t so1 = so0 + 64 * LDAB;
    const int q = lane >> 3, rr = lane & 7;
    const uint32_t lds_off = (uint32_t)(((q & 1) * 8 + rr) * LDAB + (q >> 1) * 16);
    const uint32_t am_off = (uint32_t)(warp_m * 32) * LDAB + lds_off;
    const uint32_t bn_off = 128 * LDAB + (uint32_t)(warp_n * 64) * LDAB + lds_off;

    auto load_chunk = [&](int kc, int stg) {
        const size_t g0 = (size_t)r0 * (DDIM * 2) + (size_t)kc * 64 + p0 * 16;
        const size_t g1 = g0 + (size_t)64 * (DDIM * 2);
        const uint32_t b = s0 + stg * SIMSTG;
        CP16(b + so0,              Ag + g0);
        CP16(b + so1,              Ag + g1);
        CP16(b + 128 * LDAB + so0, Bg + g0);
        CP16(b + 128 * LDAB + so1, Bg + g1);
        CPCOMMIT();
    };

    load_chunk(0, 0);
    load_chunk(1, 1);
    int cur = 0;
    for (int kc = 0; kc < 16; kc++) {
        if (kc < 15) { CPWAIT(1); } else { CPWAIT(0); }
        __syncthreads();
        if (kc + 2 < 16) {
            int iss = cur + 2; if (iss >= 3) iss -= 3;
            load_chunk(kc + 2, iss);
        }
        const uint32_t b = s0 + cur * SIMSTG;
        const uint32_t a_base = b + am_off;
        const uint32_t b_base = b + bn_off;
#pragma unroll
        for (int kk = 0; kk < 2; kk++) {
            uint32_t af[2][4];
            ldsm_x4(af[0], a_base + kk * 32);
            ldsm_x4(af[1], a_base + 16 * LDAB + kk * 32);
#pragma unroll
            for (int n2 = 0; n2 < 4; n2++) {
                uint32_t bf[4];
                ldsm_x4(bf, b_base + n2 * 16 * LDAB + kk * 32);
#pragma unroll
                for (int mt = 0; mt < 2; mt++)
#pragma unroll
                    for (int u = 0; u < 2; u++)
                        mma16816(acc[mt][n2 * 2 + u], af[mt], bf[u], bf[u + 2]);
            }
        }
        cur = (cur + 1 == 3) ? 0 : cur + 1;
    }
    __syncthreads();   // smem reusable after this
}

// exp + row/col reductions
__device__ __forceinline__ void sim_reduce(float (&acc)[2][8][4], char* sm,
                                           int lane, int warp_m, int warp_n,
                                           bool do_col) {
    float* rs_sm = (float*)sm;
    float* cs_sm = (float*)(sm + 1024);
    const float C = 2.8853900817779268f;  // 2 / ln2
    float rs_acc[2][2] = {};
    float cs2[8][2];
    if (do_col)
#pragma unroll
        for (int nt = 0; nt < 8; nt++) cs2[nt][0] = cs2[nt][1] = 0.0f;

#pragma unroll
    for (int mt = 0; mt < 2; mt++)
#pragma unroll
        for (int nt = 0; nt < 8; nt++) {
            float e0 = fast_exp2(acc[mt][nt][0] * C);
            float e1 = fast_exp2(acc[mt][nt][1] * C);
            float e2 = fast_exp2(acc[mt][nt][2] * C);
            float e3 = fast_exp2(acc[mt][nt][3] * C);
            rs_acc[mt][0] += e0 + e1;
            rs_acc[mt][1] += e2 + e3;
            if (do_col) { cs2[nt][0] += e0 + e2; cs2[nt][1] += e1 + e3; }
        }

#pragma unroll
    for (int mt = 0; mt < 2; mt++)
#pragma unroll
        for (int half = 0; half < 2; half++) {
            float v = rs_acc[mt][half];
            v += __shfl_xor_sync(0xffffffffu, v, 1);
            v += __shfl_xor_sync(0xffffffffu, v, 2);
            if ((lane & 3) == 0) {
                int row = warp_m * 32 + mt * 16 + half * 8 + (lane >> 2);
                rs_sm[row * 2 + warp_n] = v;
            }
        }
    if (do_col) {
#pragma unroll
        for (int nt = 0; nt < 8; nt++)
#pragma unroll
            for (int e = 0; e < 2; e++) {
                float v = cs2[nt][e];
                v += __shfl_xor_sync(0xffffffffu, v, 4);
                v += __shfl_xor_sync(0xffffffffu, v, 8);
                v += __shfl_xor_sync(0xffffffffu, v, 16);
                if (lane < 4) {
                    int col = warp_n * 64 + nt * 8 + lane * 2 + e;
                    cs_sm[warp_m * 128 + col] = v;
                }
            }
    }
    __syncthreads();
}

// S12 kernel: all tiles; rowsums -> rspart, colsums -> cspart
__global__ void __launch_bounds__(256)
sim12_kernel(const __nv_bfloat16* __restrict__ A, const __nv_bfloat16* __restrict__ B,
             float* __restrict__ rspart, float* __restrict__ cspart) {
    extern __shared__ __align__(128) char dynsm[];
    const int tid = threadIdx.x, lane = tid & 31, wid = tid >> 5;
    const int warp_m = wid & 3, warp_n = wid >> 2;
    const int rb = blockIdx.y, cb = blockIdx.x;

    float acc[2][8][4] = {};
    sim_tile_mma((const char*)(A + (size_t)rb * TS * DDIM),
                 (const char*)(B + (size_t)cb * TS * DDIM),
                 smem_u32(dynsm), acc, tid, lane, warp_m, warp_n);
    sim_reduce(acc, dynsm, lane, warp_m, warp_n, true);

    float* rs_sm = (float*)dynsm;
    float* cs_sm = (float*)(dynsm + 1024);
    if (tid < TS) {
        rspart[(size_t)(rb * TS + tid) * NBLK + cb] = rs_sm[tid * 2] + rs_sm[tid * 2 + 1];
        cspart[(size_t)(cb * TS + tid) * NBLK + rb] =
            cs_sm[tid] + cs_sm[128 + tid] + cs_sm[256 + tid] + cs_sm[384 + tid];
    }
}

// Fused symmetric kernel (S11 at z=0, S22 at z=1): upper-triangular tiles only.
__global__ void __launch_bounds__(256)
simsym_kernel(const __nv_bfloat16* __restrict__ A1, const __nv_bfloat16* __restrict__ A2,
              float* __restrict__ rs1, float* __restrict__ rs2) {
    const __nv_bfloat16* A = blockIdx.z ? A2 : A1;
    float* rspart = blockIdx.z ? rs2 : rs1;

    // decode upper-triangular (rb, cb), cb >= rb, from linear blockIdx.x
    const int idx = blockIdx.x;
    int rb = (int)(NBLK + 0.5f - sqrtf((NBLK + 0.5f) * (NBLK + 0.5f) - 2.0f * idx));
    if (rb < 0) rb = 0;
    if (rb > NBLK - 1) rb = NBLK - 1;
#define TRI_BASE(r) ((r) * NBLK - ((r) * ((r) - 1)) / 2)
    while (rb + 1 <= NBLK - 1 && TRI_BASE(rb + 1) <= idx) rb++;
    while (rb > 0 && TRI_BASE(rb) > idx) rb--;
    const int cb = rb + (idx - TRI_BASE(rb));
#undef TRI_BASE

    extern __shared__ __align__(128) char dynsm[];
    const int tid = threadIdx.x, lane = tid & 31, wid = tid >> 5;
    const int warp_m = wid & 3, warp_n = wid >> 2;
    const bool diag = (cb == rb);

    float acc[2][8][4] = {};
    sim_tile_mma((const char*)(A + (size_t)rb * TS * DDIM),
                 (const char*)(A + (size_t)cb * TS * DDIM),
                 smem_u32(dynsm), acc, tid, lane, warp_m, warp_n);
    sim_reduce(acc, dynsm, lane, warp_m, warp_n, !diag);

    float* rs_sm = (float*)dynsm;
    float* cs_sm = (float*)(dynsm + 1024);
    if (tid < TS) {
        rspart[(size_t)(rb * TS + tid) * NBLK + cb] = rs_sm[tid * 2] + rs_sm[tid * 2 + 1];
        if (!diag)
            rspart[(size_t)(cb * TS + tid) * NBLK + rb] =
                cs_sm[tid] + cs_sm[128 + tid] + cs_sm[256 + tid] + cs_sm[384 + tid];
    }
}

// ---------------- row L2-normalize -> fp32 + bf16 outputs -----------------
__global__ void __launch_bounds__(256)
normalize_kernel(const float* __restrict__ H, float* __restrict__ O,
                 __nv_bfloat16* __restrict__ Ob) {
    const int row  = blockIdx.x * 8 + (threadIdx.x >> 5);
    const int lane = threadIdx.x & 31;
    const float4* hp = (const float4*)(H + (size_t)row * DDIM);
    float4* op = (float4*)(O + (size_t)row * DDIM);
    float4 v[4];
    float ss = 0.0f;
#pragma unroll
    for (int m = 0; m < 4; m++) {
        v[m] = hp[lane + 32 * m];
        ss += v[m].x * v[m].x + v[m].y * v[m].y + v[m].z * v[m].z + v[m].w * v[m].w;
    }
#pragma unroll
    for (int o = 16; o > 0; o >>= 1) ss += __shfl_xor_sync(0xffffffffu, ss, o);
    const float inv = 1.0f / fmaxf(sqrtf(ss), 1e-12f);
#pragma unroll
    for (int m = 0; m < 4; m++) {
        float4 w = v[m];
        w.x *= inv; w.y *= inv; w.z *= inv; w.w *= inv;
        op[lane + 32 * m] = w;
        __nv_bfloat162 p0 = __floats2bfloat162_rn(w.x, w.y);
        __nv_bfloat162 p1 = __floats2bfloat162_rn(w.z, w.w);
        *(uint2*)(Ob + (size_t)row * DDIM + (lane + 32 * m) * 4) =
            make_uint2(*(uint32_t*)&p0, *(uint32_t*)&p1);
    }
}

__global__ void __launch_bounds__(256)
d12_kernel(const float* __restrict__ N1, const float* __restrict__ N2,
           float* __restrict__ d12) {
    const int row  = blockIdx.x * 8 + (threadIdx.x >> 5);
    const int lane = threadIdx.x & 31;
    const float4* a = (const float4*)(N1 + (size_t)row * DDIM);
    const float4* b = (const float4*)(N2 + (size_t)row * DDIM);
    float s = 0.0f;
#pragma unroll
    for (int m = 0; m < 4; m++) {
        float4 x = a[lane + 32 * m], y = b[lane + 32 * m];
        s += x.x * y.x + x.y * y.y + x.z * y.z + x.w * y.w;
    }
#pragma unroll
    for (int o = 16; o > 0; o >>= 1) s += __shfl_xor_sync(0xffffffffu, s, o);
    if (lane == 0) d12[row] = s;
}

__global__ void __launch_bounds__(256)
rowloss_kernel(const float* __restrict__ rs11p, const float* __restrict__ rs22p,
               const float* __restrict__ rs12p, const float* __restrict__ cs12p,
               const float* __restrict__ d12, float* __restrict__ loss) {
    const int row  = blockIdx.x * 8 + (threadIdx.x >> 5);
    const int lane = threadIdx.x & 31;
    float s11 = 0.0f, s22 = 0.0f, s12 = 0.0f, c12 = 0.0f;
    for (int m = lane; m < NBLK; m += 32) {
        const size_t o = (size_t)row * NBLK + m;
        s11 += rs11p[o];
        s22 += rs22p[o];
        s12 += rs12p[o];
        c12 += cs12p[o];
    }
#pragma unroll
    for (int o = 16; o > 0; o >>= 1) {
        s11 += __shfl_xor_sync(0xffffffffu, s11, o);
        s22 += __shfl_xor_sync(0xffffffffu, s22, o);
        s12 += __shfl_xor_sync(0xffffffffu, s12, o);
        c12 += __shfl_xor_sync(0xffffffffu, c12, o);
    }
    if (lane == 0) {
        const float E2 = 7.38905609893065f;   // exp(1/tau)
        const float den1 = s11 + s12 - E2;
        const float den2 = s22 + c12 - E2;
        loss[row] = -2.0f * d12[row] + 0.5f * (__logf(den1) + __logf(den2));
    }
}

__global__ void __launch_bounds__(1024)
final_kernel(const float* __restrict__ loss, float* __restrict__ out) {
    __shared__ float sm[1024];
    const int t = threadIdx.x;
    float s = 0.0f;
    for (int i = t; i < NROWS; i += 1024) s += loss[i];
    sm[t] = s;
    __syncthreads();
    for (int o = 512; o > 0; o >>= 1) {
        if (t < o) sm[t] += sm[t + o];
        __syncthreads();
    }
    if (t == 0) out[0] = sm[0] * (1.0f / NROWS);
}

// ---------------- launch ----------------------------------------------------
extern "C" void kernel_launch(void* const* d_in, const int* in_sizes, int n_in,
                              void* d_out, int out_size) {
    const float* pri = (const float*)d_in[0];
    const float* aux = (const float*)d_in[1];
    const float* W1  = (const float*)d_in[2];
    const float* b1  = (const float*)d_in[3];
    const float* W2  = (const float*)d_in[4];
    const float* b2  = (const float*)d_in[5];
    float* out = (float*)d_out;

    __nv_bfloat16 *Zh, *Zl, *Th, *Tl, *W1h, *W1l, *W2h, *W2l, *B1, *B2;
    float *H, *N1, *N2, *rs11p, *rs22p, *rs12p, *cs12p, *d12, *loss;
    cudaGetSymbolAddress((void**)&Zh,  g_Zh);
    cudaGetSymbolAddress((void**)&Zl,  g_Zl);
    cudaGetSymbolAddress((void**)&Th,  g_Th);
    cudaGetSymbolAddress((void**)&Tl,  g_Tl);
    cudaGetSymbolAddress((void**)&W1h, g_W1h);
    cudaGetSymbolAddress((void**)&W1l, g_W1l);
    cudaGetSymbolAddress((void**)&W2h, g_W2h);
    cudaGetSymbolAddress((void**)&W2l, g_W2l);
    cudaGetSymbolAddress((void**)&H,   g_H);
    cudaGetSymbolAddress((void**)&N1,  g_N1);
    cudaGetSymbolAddress((void**)&N2,  g_N2);
    cudaGetSymbolAddress((void**)&B1,  g_B1);
    cudaGetSymbolAddress((void**)&B2,  g_B2);
    cudaGetSymbolAddress((void**)&rs11p, g_rs11p);
    cudaGetSymbolAddress((void**)&rs22p, g_rs22p);
    cudaGetSymbolAddress((void**)&rs12p, g_rs12p);
    cudaGetSymbolAddress((void**)&cs12p, g_cs12p);
    cudaGetSymbolAddress((void**)&d12,  g_d12);
    cudaGetSymbolAddress((void**)&loss, g_loss);

    const int simSmem  = 3 * SIMSTG;    // 61440
    const int projSmem = 2 * PROJSTG;   // 81920
    cudaFuncSetAttribute(proj_mma_kernel<true,  true >,
                         cudaFuncAttributeMaxDynamicSharedMemorySize, projSmem);
    cudaFuncSetAttribute(proj_mma_kernel<false, false>,
                         cudaFuncAttributeMaxDynamicSharedMemorySize, projSmem);
    cudaFuncSetAttribute(sim12_kernel,
                         cudaFuncAttributeMaxDynamicSharedMemorySize, simSmem);
    cudaFuncSetAttribute(simsym_kernel,
                         cudaFuncAttributeMaxDynamicSharedMemorySize, simSmem);

    const dim3 pg(DDIM / TS, NROWS / TS);   // (4, 64)
    const dim3 sg(NBLK, NBLK);              // (64, 64)
    const dim3 syg(NSYM, 1, 2);             // (2080, 1, 2)
    const int nW = DDIM * DDIM / 1024;
    const int nZ = NROWS * DDIM / 1024;

    split_kernel<<<nW, 256>>>(W1, W1h, W1l);
    split_kernel<<<nW, 256>>>(W2, W2h, W2l);

    split_kernel<<<nZ, 256>>>(pri, Zh, Zl);
    proj_mma_kernel<true,  true ><<<pg, 256, projSmem>>>(Zh, Zl, W1h, W1l, b1, nullptr, Th, Tl);
    proj_mma_kernel<false, false><<<pg, 256, projSmem>>>(Th, Tl, W2h, W2l, b2, H, nullptr, nullptr);
    normalize_kernel<<<NROWS / 8, 256>>>(H, N1, B1);
    split_kernel<<<nZ, 256>>>(aux, Zh, Zl);
    proj_mma_kernel<true,  true ><<<pg, 256, projSmem>>>(Zh, Zl, W1h, W1l, b1, nullptr, Th, Tl);
    proj_mma_kernel<false, false><<<pg, 256, projSmem>>>(Th, Tl, W2h, W2l, b2, H, nullptr, nullptr);
    normalize_kernel<<<NROWS / 8, 256>>>(H, N2, B2);

    d12_kernel<<<NROWS / 8, 256>>>(N1, N2, d12);

    simsym_kernel<<<syg, 256, simSmem>>>(B1, B2, rs11p, rs22p);
    sim12_kernel <<<sg,  256, simSmem>>>(B1, B2, rs12p, cs12p);

    rowloss_kernel<<<NROWS / 8, 256>>>(rs11p, rs22p, rs12p, cs12p, d12, loss);
    final_kernel<<<1, 1024>>>(loss, out);
}

// round 6
// speedup vs baseline: 7.4822x; 1.0740x over previous
#include <cuda_runtime.h>
#include <cuda_bf16.h>
#include <math.h>
#include <stdint.h>

#define NROWS 8192
#define DDIM  512
#define TS    128
#define NBLK  (NROWS / TS)   // 64
#define LDAB  80             // smem row stride (bytes): 32 bf16 + 16B pad
#define SIMSTG (2 * 128 * LDAB)   // 20480 per sim stage
#define PROJSTG (4 * 128 * LDAB)  // 40960 per proj stage
#define NSYM  (NBLK * (NBLK + 1) / 2)   // 2080
#define ZSTRIDE ((size_t)NROWS * DDIM)

// ---------------- device scratch ----------------
__device__ __nv_bfloat16 g_Zh[2 * NROWS * DDIM];
__device__ __nv_bfloat16 g_Zl[2 * NROWS * DDIM];
__device__ __nv_bfloat16 g_Th[2 * NROWS * DDIM];
__device__ __nv_bfloat16 g_Tl[2 * NROWS * DDIM];
__device__ __nv_bfloat16 g_W1h[DDIM * DDIM];
__device__ __nv_bfloat16 g_W1l[DDIM * DDIM];
__device__ __nv_bfloat16 g_W2h[DDIM * DDIM];
__device__ __nv_bfloat16 g_W2l[DDIM * DDIM];
__device__ float g_H [2 * NROWS * DDIM];
__device__ float g_N1[NROWS * DDIM];
__device__ float g_N2[NROWS * DDIM];
__device__ __nv_bfloat16 g_B1[NROWS * DDIM];
__device__ __nv_bfloat16 g_B2[NROWS * DDIM];
__device__ float g_rs11p[NROWS * NBLK];
__device__ float g_rs22p[NROWS * NBLK];
__device__ float g_rs12p[NROWS * NBLK];
__device__ float g_cs12p[NROWS * NBLK];
__device__ float g_d12 [NROWS];
__device__ float g_loss[NROWS];

// ====================== helpers ======================
__device__ __forceinline__ uint32_t smem_u32(const void* p) {
    uint32_t a;
    asm("{ .reg .u64 t; cvta.to.shared.u64 t, %1; cvt.u32.u64 %0, t; }"
        : "=r"(a) : "l"(p));
    return a;
}
__device__ __forceinline__ void ldsm_x4(uint32_t (&r)[4], uint32_t addr) {
    asm volatile("ldmatrix.sync.aligned.m8n8.x4.shared.b16 {%0,%1,%2,%3}, [%4];"
        : "=r"(r[0]), "=r"(r[1]), "=r"(r[2]), "=r"(r[3]) : "r"(addr));
}
__device__ __forceinline__ void mma16816(float (&d)[4], const uint32_t (&a)[4],
                                         uint32_t b0, uint32_t b1) {
    asm volatile("mma.sync.aligned.m16n8k16.row.col.f32.bf16.bf16.f32 "
        "{%0,%1,%2,%3}, {%4,%5,%6,%7}, {%8,%9}, {%0,%1,%2,%3};"
        : "+f"(d[0]), "+f"(d[1]), "+f"(d[2]), "+f"(d[3])
        : "r"(a[0]), "r"(a[1]), "r"(a[2]), "r"(a[3]), "r"(b0), "r"(b1));
}
#define CP16(dst, src) \
    asm volatile("cp.async.cg.shared.global [%0], [%1], 16;" :: "r"(dst), "l"(src))
#define CPCOMMIT() asm volatile("cp.async.commit_group;" ::: "memory")
#define CPWAIT(n)  asm volatile("cp.async.wait_group %0;" :: "n"(n) : "memory")

__device__ __forceinline__ float fast_exp2(float x) {
    float y; asm("ex2.approx.f32 %0, %1;" : "=f"(y) : "f"(x)); return y;
}
__device__ __forceinline__ void split2(float x, __nv_bfloat16& h, __nv_bfloat16& l) {
    h = __float2bfloat16(x);
    l = __float2bfloat16(x - __bfloat162float(h));
}

// ================== split kernel: fp32 -> (hi, lo) bf16 ==================
__global__ void __launch_bounds__(256)
split_kernel(const float* __restrict__ X, __nv_bfloat16* __restrict__ Hi,
             __nv_bfloat16* __restrict__ Lo) {
    const int i = (blockIdx.x * 256 + threadIdx.x) * 4;
    float4 v = *(const float4*)(X + i);
    __nv_bfloat16 h0, h1, h2, h3, l0, l1, l2, l3;
    split2(v.x, h0, l0); split2(v.y, h1, l1);
    split2(v.z, h2, l2); split2(v.w, h3, l3);
    __nv_bfloat162 hp0 = {h0, h1}, hp1 = {h2, h3};
    __nv_bfloat162 lp0 = {l0, l1}, lp1 = {l2, l3};
    *(uint2*)(Hi + i) = make_uint2(*(uint32_t*)&hp0, *(uint32_t*)&hp1);
    *(uint2*)(Lo + i) = make_uint2(*(uint32_t*)&lp0, *(uint32_t*)&lp1);
}

// ============ split-bf16 projection GEMM (2-stage cp.async, z-batched) =====
template <bool DO_ELU, bool SPLIT_OUT>
__global__ void __launch_bounds__(256, 2)
proj_mma_kernel(const __nv_bfloat16* __restrict__ Ah, const __nv_bfloat16* __restrict__ Al,
                const __nv_bfloat16* __restrict__ Wh, const __nv_bfloat16* __restrict__ Wl,
                const float* __restrict__ bias,
                float* __restrict__ Hout,
                __nv_bfloat16* __restrict__ Oh, __nv_bfloat16* __restrict__ Ol) {
    extern __shared__ __align__(128) char dynsm[];
    const uint32_t s0 = smem_u32(dynsm);

    const int tid = threadIdx.x, lane = tid & 31, wid = tid >> 5;
    const int warp_m = wid & 3, warp_n = wid >> 2;
    const int cb = blockIdx.x, rb = blockIdx.y;
    const size_t zoff = (size_t)blockIdx.z * ZSTRIDE;

    const char* Agh = (const char*)(Ah + zoff + (size_t)rb * TS * DDIM);
    const char* Agl = (const char*)(Al + zoff + (size_t)rb * TS * DDIM);
    const char* Wgh = (const char*)(Wh + (size_t)cb * TS * DDIM);
    const char* Wgl = (const char*)(Wl + (size_t)cb * TS * DDIM);

    const int r0 = tid >> 2, p0 = tid & 3;
    const uint32_t so0 = (uint32_t)(r0 * LDAB + p0 * 16);
    const uint32_t so1 = so0 + 64 * LDAB;

    const int q = lane >> 3, rr = lane & 7;
    const uint32_t lds_off = (uint32_t)(((q & 1) * 8 + rr) * LDAB + (q >> 1) * 16);
    const uint32_t am_off = (uint32_t)(warp_m * 32) * LDAB + lds_off;
    const uint32_t wn_off = (uint32_t)(warp_n * 64) * LDAB + lds_off;

    float acc[2][8][4] = {};

    auto load_chunk = [&](int kc, int stg) {
        const size_t g0 = (size_t)r0 * (DDIM * 2) + (size_t)kc * 64 + p0 * 16;
        const size_t g1 = g0 + (size_t)64 * (DDIM * 2);
        const uint32_t b = s0 + stg * PROJSTG;
        CP16(b + so0,                  Agh + g0);
        CP16(b + so1,                  Agh + g1);
        CP16(b + 128 * LDAB + so0,     Agl + g0);
        CP16(b + 128 * LDAB + so1,     Agl + g1);
        CP16(b + 2 * 128 * LDAB + so0, Wgh + g0);
        CP16(b + 2 * 128 * LDAB + so1, Wgh + g1);
        CP16(b + 3 * 128 * LDAB + so0, Wgl + g0);
        CP16(b + 3 * 128 * LDAB + so1, Wgl + g1);
        CPCOMMIT();
    };

    load_chunk(0, 0);
    for (int kc = 0; kc < 16; kc++) {
        if (kc + 1 < 16) load_chunk(kc + 1, (kc + 1) & 1);
        if (kc < 15) { CPWAIT(1); } else { CPWAIT(0); }
        __syncthreads();
        const uint32_t b = s0 + (kc & 1) * PROJSTG;
        const uint32_t ah_base = b + am_off;
        const uint32_t al_base = b + 128 * LDAB + am_off;
        const uint32_t bh_base = b + 2 * 128 * LDAB + wn_off;
        const uint32_t bl_base = b + 3 * 128 * LDAB + wn_off;
#pragma unroll
        for (int kk = 0; kk < 2; kk++) {
            uint32_t ah[2][4], al[2][4];
            ldsm_x4(ah[0], ah_base + kk * 32);
            ldsm_x4(ah[1], ah_base + 16 * LDAB + kk * 32);
            ldsm_x4(al[0], al_base + kk * 32);
            ldsm_x4(al[1], al_base + 16 * LDAB + kk * 32);
#pragma unroll
            for (int n2 = 0; n2 < 4; n2++) {
                uint32_t bh[4], bl[4];
                ldsm_x4(bh, bh_base + n2 * 16 * LDAB + kk * 32);
                ldsm_x4(bl, bl_base + n2 * 16 * LDAB + kk * 32);
#pragma unroll
                for (int mt = 0; mt < 2; mt++)
#pragma unroll
                    for (int u = 0; u < 2; u++) {
                        const int nt = n2 * 2 + u;
                        mma16816(acc[mt][nt], ah[mt], bh[u], bh[u + 2]);
                        mma16816(acc[mt][nt], ah[mt], bl[u], bl[u + 2]);
                        mma16816(acc[mt][nt], al[mt], bh[u], bh[u + 2]);
                    }
            }
        }
        __syncthreads();
    }

    // ---- epilogue ----
    const int cbase = cb * TS + warp_n * 64;
    const int rbase = rb * TS + warp_m * 32 + (lane >> 2);
#pragma unroll
    for (int mt = 0; mt < 2; mt++) {
        const int ra = rbase + mt * 16, rbb = ra + 8;
#pragma unroll
        for (int nt = 0; nt < 8; nt++) {
            const int c = cbase + nt * 8 + (lane & 3) * 2;
            const float bv0 = bias[c], bv1 = bias[c + 1];
            float x00 = acc[mt][nt][0] + bv0, x01 = acc[mt][nt][1] + bv1;
            float x10 = acc[mt][nt][2] + bv0, x11 = acc[mt][nt][3] + bv1;
            if (DO_ELU) {
                x00 = (x00 > 0.0f) ? x00 : expm1f(x00);
                x01 = (x01 > 0.0f) ? x01 : expm1f(x01);
                x10 = (x10 > 0.0f) ? x10 : expm1f(x10);
                x11 = (x11 > 0.0f) ? x11 : expm1f(x11);
            }
            if (SPLIT_OUT) {
                __nv_bfloat16 h0, h1, l0, l1;
                split2(x00, h0, l0); split2(x01, h1, l1);
                __nv_bfloat162 hp = {h0, h1}, lp = {l0, l1};
                *(uint32_t*)(Oh + zoff + (size_t)ra * DDIM + c) = *(uint32_t*)&hp;
                *(uint32_t*)(Ol + zoff + (size_t)ra * DDIM + c) = *(uint32_t*)&lp;
                split2(x10, h0, l0); split2(x11, h1, l1);
                __nv_bfloat162 hq = {h0, h1}, lq = {l0, l1};
                *(uint32_t*)(Oh + zoff + (size_t)rbb * DDIM + c) = *(uint32_t*)&hq;
                *(uint32_t*)(Ol + zoff + (size_t)rbb * DDIM + c) = *(uint32_t*)&lq;
            } else {
                *(float2*)(Hout + zoff + (size_t)ra  * DDIM + c) = make_float2(x00, x01);
                *(float2*)(Hout + zoff + (size_t)rbb * DDIM + c) = make_float2(x10, x11);
            }
        }
    }
}

// ================= similarity tile core (3-stage cp.async) =================
__device__ __forceinline__ void sim_tile_mma(const char* Ag, const char* Bg,
                                             uint32_t s0,
                                             float (&acc)[2][8][4],
                                             int tid, int lane, int warp_m, int warp_n) {
    const int r0 = tid >> 2, p0 = tid & 3;
    const uint32_t so0 = (uint32_t)(r0 * LDAB + p0 * 16);
    const uint32_t so1 = so0 + 64 * LDAB;
    const int q = lane >> 3, rr = lane & 7;
    const uint32_t lds_off = (uint32_t)(((q & 1) * 8 + rr) * LDAB + (q >> 1) * 16);
    const uint32_t am_off = (uint32_t)(warp_m * 32) * LDAB + lds_off;
    const uint32_t bn_off = 128 * LDAB + (uint32_t)(warp_n * 64) * LDAB + lds_off;

    auto load_chunk = [&](int kc, int stg) {
        const size_t g0 = (size_t)r0 * (DDIM * 2) + (size_t)kc * 64 + p0 * 16;
        const size_t g1 = g0 + (size_t)64 * (DDIM * 2);
        const uint32_t b = s0 + stg * SIMSTG;
        CP16(b + so0,              Ag + g0);
        CP16(b + so1,              Ag + g1);
        CP16(b + 128 * LDAB + so0, Bg + g0);
        CP16(b + 128 * LDAB + so1, Bg + g1);
        CPCOMMIT();
    };

    load_chunk(0, 0);
    load_chunk(1, 1);
    int cur = 0;
    for (int kc = 0; kc < 16; kc++) {
        if (kc < 15) { CPWAIT(1); } else { CPWAIT(0); }
        __syncthreads();
        if (kc + 2 < 16) {
            int iss = cur + 2; if (iss >= 3) iss -= 3;
            load_chunk(kc + 2, iss);
        }
        const uint32_t b = s0 + cur * SIMSTG;
        const uint32_t a_base = b + am_off;
        const uint32_t b_base = b + bn_off;
#pragma unroll
        for (int kk = 0; kk < 2; kk++) {
            uint32_t af[2][4];
            ldsm_x4(af[0], a_base + kk * 32);
            ldsm_x4(af[1], a_base + 16 * LDAB + kk * 32);
#pragma unroll
            for (int n2 = 0; n2 < 4; n2++) {
                uint32_t bf[4];
                ldsm_x4(bf, b_base + n2 * 16 * LDAB + kk * 32);
#pragma unroll
                for (int mt = 0; mt < 2; mt++)
#pragma unroll
                    for (int u = 0; u < 2; u++)
                        mma16816(acc[mt][n2 * 2 + u], af[mt], bf[u], bf[u + 2]);
            }
        }
        cur = (cur + 1 == 3) ? 0 : cur + 1;
    }
    __syncthreads();
}

// exp + row/col reductions
__device__ __forceinline__ void sim_reduce(float (&acc)[2][8][4], char* sm,
                                           int lane, int warp_m, int warp_n,
                                           bool do_col) {
    float* rs_sm = (float*)sm;
    float* cs_sm = (float*)(sm + 1024);
    const float C = 2.8853900817779268f;  // 2 / ln2
    float rs_acc[2][2] = {};
    float cs2[8][2];
    if (do_col)
#pragma unroll
        for (int nt = 0; nt < 8; nt++) cs2[nt][0] = cs2[nt][1] = 0.0f;

#pragma unroll
    for (int mt = 0; mt < 2; mt++)
#pragma unroll
        for (int nt = 0; nt < 8; nt++) {
            float e0 = fast_exp2(acc[mt][nt][0] * C);
            float e1 = fast_exp2(acc[mt][nt][1] * C);
            float e2 = fast_exp2(acc[mt][nt][2] * C);
            float e3 = fast_exp2(acc[mt][nt][3] * C);
            rs_acc[mt][0] += e0 + e1;
            rs_acc[mt][1] += e2 + e3;
            if (do_col) { cs2[nt][0] += e0 + e2; cs2[nt][1] += e1 + e3; }
        }

#pragma unroll
    for (int mt = 0; mt < 2; mt++)
#pragma unroll
        for (int half = 0; half < 2; half++) {
            float v = rs_acc[mt][half];
            v += __shfl_xor_sync(0xffffffffu, v, 1);
            v += __shfl_xor_sync(0xffffffffu, v, 2);
            if ((lane & 3) == 0) {
                int row = warp_m * 32 + mt * 16 + half * 8 + (lane >> 2);
                rs_sm[row * 2 + warp_n] = v;
            }
        }
    if (do_col) {
#pragma unroll
        for (int nt = 0; nt < 8; nt++)
#pragma unroll
            for (int e = 0; e < 2; e++) {
                float v = cs2[nt][e];
                v += __shfl_xor_sync(0xffffffffu, v, 4);
                v += __shfl_xor_sync(0xffffffffu, v, 8);
                v += __shfl_xor_sync(0xffffffffu, v, 16);
                if (lane < 4) {
                    int col = warp_n * 64 + nt * 8 + lane * 2 + e;
                    cs_sm[warp_m * 128 + col] = v;
                }
            }
    }
    __syncthreads();
}

// ============ unified similarity kernel: all 8256 tiles in ONE launch =======
// bid < 2*NSYM: symmetric tiles (z = bid/NSYM picks B1/B2), upper-triangular.
// else:         S12 tiles, linear rb*64+cb.
__global__ void __launch_bounds__(256, 2)
sim_all_kernel(const __nv_bfloat16* __restrict__ B1, const __nv_bfloat16* __restrict__ B2,
               float* __restrict__ rs11p, float* __restrict__ rs22p,
               float* __restrict__ rs12p, float* __restrict__ cs12p) {
    extern __shared__ __align__(128) char dynsm[];
    const int bid = blockIdx.x;
    const int tid = threadIdx.x, lane = tid & 31, wid = tid >> 5;
    const int warp_m = wid & 3, warp_n = wid >> 2;

    const __nv_bfloat16 *A, *B;
    float *rsp, *csp;
    int rb, cb;
    bool diag = false, sym;

    if (bid < 2 * NSYM) {
        sym = true;
        const int z = (bid >= NSYM) ? 1 : 0;
        const int idx = bid - z * NSYM;
        int r = (int)(NBLK + 0.5f - sqrtf((NBLK + 0.5f) * (NBLK + 0.5f) - 2.0f * idx));
        if (r < 0) r = 0;
        if (r > NBLK - 1) r = NBLK - 1;
#define TRI_BASE(x) ((x) * NBLK - ((x) * ((x) - 1)) / 2)
        while (r + 1 <= NBLK - 1 && TRI_BASE(r + 1) <= idx) r++;
        while (r > 0 && TRI_BASE(r) > idx) r--;
        rb = r;
        cb = r + (idx - TRI_BASE(r));
#undef TRI_BASE
        A = z ? B2 : B1;
        B = A;
        rsp = z ? rs22p : rs11p;
        csp = nullptr;
        diag = (rb == cb);
    } else {
        sym = false;
        const int idx = bid - 2 * NSYM;
        rb = idx >> 6;
        cb = idx & (NBLK - 1);
        A = B1; B = B2;
        rsp = rs12p; csp = cs12p;
    }

    float acc[2][8][4] = {};
    sim_tile_mma((const char*)(A + (size_t)rb * TS * DDIM),
                 (const char*)(B + (size_t)cb * TS * DDIM),
                 smem_u32(dynsm), acc, tid, lane, warp_m, warp_n);
    sim_reduce(acc, dynsm, lane, warp_m, warp_n, !diag);

    float* rs_sm = (float*)dynsm;
    float* cs_sm = (float*)(dynsm + 1024);
    if (tid < TS) {
        rsp[(size_t)(rb * TS + tid) * NBLK + cb] = rs_sm[tid * 2] + rs_sm[tid * 2 + 1];
        if (!diag) {
            const float ctot = cs_sm[tid] + cs_sm[128 + tid] +
                               cs_sm[256 + tid] + cs_sm[384 + tid];
            if (sym) rsp[(size_t)(cb * TS + tid) * NBLK + rb] = ctot;
            else     csp[(size_t)(cb * TS + tid) * NBLK + rb] = ctot;
        } else if (!sym) {
            // diag only occurs in sym path; nothing here
        }
    }
    // note: S12 diag (rb==cb) still needs colsum: handled since diag only true for sym
}

// ---------------- row L2-normalize (z-batched) -----------------
__global__ void __launch_bounds__(256)
normalize_kernel(const float* __restrict__ H, float* __restrict__ O1,
                 float* __restrict__ O2, __nv_bfloat16* __restrict__ Ob1,
                 __nv_bfloat16* __restrict__ Ob2) {
    const int z = blockIdx.y;
    const int row  = blockIdx.x * 8 + (threadIdx.x >> 5);
    const int lane = threadIdx.x & 31;
    float* O = z ? O2 : O1;
    __nv_bfloat16* Ob = z ? Ob2 : Ob1;
    const float4* hp = (const float4*)(H + (size_t)z * ZSTRIDE + (size_t)row * DDIM);
    float4* op = (float4*)(O + (size_t)row * DDIM);
    float4 v[4];
    float ss = 0.0f;
#pragma unroll
    for (int m = 0; m < 4; m++) {
        v[m] = hp[lane + 32 * m];
        ss += v[m].x * v[m].x + v[m].y * v[m].y + v[m].z * v[m].z + v[m].w * v[m].w;
    }
#pragma unroll
    for (int o = 16; o > 0; o >>= 1) ss += __shfl_xor_sync(0xffffffffu, ss, o);
    const float inv = 1.0f / fmaxf(sqrtf(ss), 1e-12f);
#pragma unroll
    for (int m = 0; m < 4; m++) {
        float4 w = v[m];
        w.x *= inv; w.y *= inv; w.z *= inv; w.w *= inv;
        op[lane + 32 * m] = w;
        __nv_bfloat162 p0 = __floats2bfloat162_rn(w.x, w.y);
        __nv_bfloat162 p1 = __floats2bfloat162_rn(w.z, w.w);
        *(uint2*)(Ob + (size_t)row * DDIM + (lane + 32 * m) * 4) =
            make_uint2(*(uint32_t*)&p0, *(uint32_t*)&p1);
    }
}

__global__ void __launch_bounds__(256)
d12_kernel(const float* __restrict__ N1, const float* __restrict__ N2,
           float* __restrict__ d12) {
    const int row  = blockIdx.x * 8 + (threadIdx.x >> 5);
    const int lane = threadIdx.x & 31;
    const float4* a = (const float4*)(N1 + (size_t)row * DDIM);
    const float4* b = (const float4*)(N2 + (size_t)row * DDIM);
    float s = 0.0f;
#pragma unroll
    for (int m = 0; m < 4; m++) {
        float4 x = a[lane + 32 * m], y = b[lane + 32 * m];
        s += x.x * y.x + x.y * y.y + x.z * y.z + x.w * y.w;
    }
#pragma unroll
    for (int o = 16; o > 0; o >>= 1) s += __shfl_xor_sync(0xffffffffu, s, o);
    if (lane == 0) d12[row] = s;
}

__global__ void __launch_bounds__(256)
rowloss_kernel(const float* __restrict__ rs11p, const float* __restrict__ rs22p,
               const float* __restrict__ rs12p, const float* __restrict__ cs12p,
               const float* __restrict__ d12, float* __restrict__ loss) {
    const int row  = blockIdx.x * 8 + (threadIdx.x >> 5);
    const int lane = threadIdx.x & 31;
    float s11 = 0.0f, s22 = 0.0f, s12 = 0.0f, c12 = 0.0f;
    for (int m = lane; m < NBLK; m += 32) {
        const size_t o = (size_t)row * NBLK + m;
        s11 += rs11p[o];
        s22 += rs22p[o];
        s12 += rs12p[o];
        c12 += cs12p[o];
    }
#pragma unroll
    for (int o = 16; o > 0; o >>= 1) {
        s11 += __shfl_xor_sync(0xffffffffu, s11, o);
        s22 += __shfl_xor_sync(0xffffffffu, s22, o);
        s12 += __shfl_xor_sync(0xffffffffu, s12, o);
        c12 += __shfl_xor_sync(0xffffffffu, c12, o);
    }
    if (lane == 0) {
        const float E2 = 7.38905609893065f;   // exp(1/tau)
        const float den1 = s11 + s12 - E2;
        const float den2 = s22 + c12 - E2;
        loss[row] = -2.0f * d12[row] + 0.5f * (__logf(den1) + __logf(den2));
    }
}

__global__ void __launch_bounds__(1024)
final_kernel(const float* __restrict__ loss, float* __restrict__ out) {
    __shared__ float sm[1024];
    const int t = threadIdx.x;
    float s = 0.0f;
    for (int i = t; i < NROWS; i += 1024) s += loss[i];
    sm[t] = s;
    __syncthreads();
    for (int o = 512; o > 0; o >>= 1) {
        if (t < o) sm[t] += sm[t + o];
        __syncthreads();
    }
    if (t == 0) out[0] = sm[0] * (1.0f / NROWS);
}

// ---------------- launch ----------------------------------------------------
extern "C" void kernel_launch(void* const* d_in, const int* in_sizes, int n_in,
                              void* d_out, int out_size) {
    const float* pri = (const float*)d_in[0];
    const float* aux = (const float*)d_in[1];
    const float* W1  = (const float*)d_in[2];
    const float* b1  = (const float*)d_in[3];
    const float* W2  = (const float*)d_in[4];
    const float* b2  = (const float*)d_in[5];
    float* out = (float*)d_out;

    __nv_bfloat16 *Zh, *Zl, *Th, *Tl, *W1h, *W1l, *W2h, *W2l, *B1, *B2;
    float *H, *N1, *N2, *rs11p, *rs22p, *rs12p, *cs12p, *d12, *loss;
    cudaGetSymbolAddress((void**)&Zh,  g_Zh);
    cudaGetSymbolAddress((void**)&Zl,  g_Zl);
    cudaGetSymbolAddress((void**)&Th,  g_Th);
    cudaGetSymbolAddress((void**)&Tl,  g_Tl);
    cudaGetSymbolAddress((void**)&W1h, g_W1h);
    cudaGetSymbolAddress((void**)&W1l, g_W1l);
    cudaGetSymbolAddress((void**)&W2h, g_W2h);
    cudaGetSymbolAddress((void**)&W2l, g_W2l);
    cudaGetSymbolAddress((void**)&H,   g_H);
    cudaGetSymbolAddress((void**)&N1,  g_N1);
    cudaGetSymbolAddress((void**)&N2,  g_N2);
    cudaGetSymbolAddress((void**)&B1,  g_B1);
    cudaGetSymbolAddress((void**)&B2,  g_B2);
    cudaGetSymbolAddress((void**)&rs11p, g_rs11p);
    cudaGetSymbolAddress((void**)&rs22p, g_rs22p);
    cudaGetSymbolAddress((void**)&rs12p, g_rs12p);
    cudaGetSymbolAddress((void**)&cs12p, g_cs12p);
    cudaGetSymbolAddress((void**)&d12,  g_d12);
    cudaGetSymbolAddress((void**)&loss, g_loss);

    const int simSmem  = 3 * SIMSTG;    // 61440
    const int projSmem = 2 * PROJSTG;   // 81920
    cudaFuncSetAttribute(proj_mma_kernel<true,  true >,
                         cudaFuncAttributeMaxDynamicSharedMemorySize, projSmem);
    cudaFuncSetAttribute(proj_mma_kernel<false, false>,
                         cudaFuncAttributeMaxDynamicSharedMemorySize, projSmem);
    cudaFuncSetAttribute(sim_all_kernel,
                         cudaFuncAttributeMaxDynamicSharedMemorySize, simSmem);

    const dim3 pg(DDIM / TS, NROWS / TS, 2);   // (4, 64, 2)
    const int simBlocks = 2 * NSYM + NBLK * NBLK;   // 8256
    const int nW = DDIM * DDIM / 1024;
    const int nZ = NROWS * DDIM / 1024;

    split_kernel<<<nW, 256>>>(W1, W1h, W1l);
    split_kernel<<<nW, 256>>>(W2, W2h, W2l);
    split_kernel<<<nZ, 256>>>(pri, Zh, Zl);
    split_kernel<<<nZ, 256>>>(aux, Zh + ZSTRIDE, Zl + ZSTRIDE);

    proj_mma_kernel<true,  true ><<<pg, 256, projSmem>>>(Zh, Zl, W1h, W1l, b1,
                                                         nullptr, Th, Tl);
    proj_mma_kernel<false, false><<<pg, 256, projSmem>>>(Th, Tl, W2h, W2l, b2,
                                                         H, nullptr, nullptr);
    normalize_kernel<<<dim3(NROWS / 8, 2), 256>>>(H, N1, N2, B1, B2);

    d12_kernel<<<NROWS / 8, 256>>>(N1, N2, d12);

    sim_all_kernel<<<simBlocks, 256, simSmem>>>(B1, B2, rs11p, rs22p, rs12p, cs12p);

    rowloss_kernel<<<NROWS / 8, 256>>>(rs11p, rs22p, rs12p, cs12p, d12, loss);
    final_kernel<<<1, 1024>>>(loss, out);
}

// round 7
// speedup vs baseline: 7.9784x; 1.0663x over previous
#include <cuda_runtime.h>
#include <cuda_bf16.h>
#include <cuda_fp8.h>
#include <math.h>
#include <stdint.h>

#define NROWS 8192
#define DDIM  512
#define TS    128
#define NBLK  (NROWS / TS)   // 64
#define LDAB  80             // smem row stride (bytes)
#define SIMSTG (2 * 128 * LDAB)   // 20480 per sim stage
#define PROJSTG (4 * 128 * LDAB)  // 40960 per proj stage
#define NSYM  (NBLK * (NBLK + 1) / 2)   // 2080
#define ZSTRIDE ((size_t)NROWS * DDIM)
#define FP8SCALE 16.0f

// ---------------- device scratch ----------------
__device__ __nv_bfloat16 g_Zh[2 * NROWS * DDIM];
__device__ __nv_bfloat16 g_Zl[2 * NROWS * DDIM];
__device__ __nv_bfloat16 g_Th[2 * NROWS * DDIM];
__device__ __nv_bfloat16 g_Tl[2 * NROWS * DDIM];
__device__ __nv_bfloat16 g_W1h[DDIM * DDIM];
__device__ __nv_bfloat16 g_W1l[DDIM * DDIM];
__device__ __nv_bfloat16 g_W2h[DDIM * DDIM];
__device__ __nv_bfloat16 g_W2l[DDIM * DDIM];
__device__ float g_H [2 * NROWS * DDIM];
__device__ float g_N1[NROWS * DDIM];
__device__ float g_N2[NROWS * DDIM];
__device__ uint8_t g_F1[NROWS * DDIM];   // fp8 e4m3, scaled by 16
__device__ uint8_t g_F2[NROWS * DDIM];
__device__ float g_rs11p[NROWS * NBLK];
__device__ float g_rs22p[NROWS * NBLK];
__device__ float g_rs12p[NROWS * NBLK];
__device__ float g_cs12p[NROWS * NBLK];
__device__ float g_d12 [NROWS];
__device__ float g_loss[NROWS];

// ====================== helpers ======================
__device__ __forceinline__ uint32_t smem_u32(const void* p) {
    uint32_t a;
    asm("{ .reg .u64 t; cvta.to.shared.u64 t, %1; cvt.u32.u64 %0, t; }"
        : "=r"(a) : "l"(p));
    return a;
}
__device__ __forceinline__ void ldsm_x4(uint32_t (&r)[4], uint32_t addr) {
    asm volatile("ldmatrix.sync.aligned.m8n8.x4.shared.b16 {%0,%1,%2,%3}, [%4];"
        : "=r"(r[0]), "=r"(r[1]), "=r"(r[2]), "=r"(r[3]) : "r"(addr));
}
__device__ __forceinline__ void mma16816(float (&d)[4], const uint32_t (&a)[4],
                                         uint32_t b0, uint32_t b1) {
    asm volatile("mma.sync.aligned.m16n8k16.row.col.f32.bf16.bf16.f32 "
        "{%0,%1,%2,%3}, {%4,%5,%6,%7}, {%8,%9}, {%0,%1,%2,%3};"
        : "+f"(d[0]), "+f"(d[1]), "+f"(d[2]), "+f"(d[3])
        : "r"(a[0]), "r"(a[1]), "r"(a[2]), "r"(a[3]), "r"(b0), "r"(b1));
}
__device__ __forceinline__ void mma16832_fp8(float (&d)[4], const uint32_t (&a)[4],
                                             uint32_t b0, uint32_t b1) {
    asm volatile("mma.sync.aligned.m16n8k32.row.col.f32.e4m3.e4m3.f32 "
        "{%0,%1,%2,%3}, {%4,%5,%6,%7}, {%8,%9}, {%0,%1,%2,%3};"
        : "+f"(d[0]), "+f"(d[1]), "+f"(d[2]), "+f"(d[3])
        : "r"(a[0]), "r"(a[1]), "r"(a[2]), "r"(a[3]), "r"(b0), "r"(b1));
}
#define CP16(dst, src) \
    asm volatile("cp.async.cg.shared.global [%0], [%1], 16;" :: "r"(dst), "l"(src))
#define CPCOMMIT() asm volatile("cp.async.commit_group;" ::: "memory")
#define CPWAIT(n)  asm volatile("cp.async.wait_group %0;" :: "n"(n) : "memory")

__device__ __forceinline__ float fast_exp2(float x) {
    float y; asm("ex2.approx.f32 %0, %1;" : "=f"(y) : "f"(x)); return y;
}
__device__ __forceinline__ void split2(float x, __nv_bfloat16& h, __nv_bfloat16& l) {
    h = __float2bfloat16(x);
    l = __float2bfloat16(x - __bfloat162float(h));
}

// ================== split kernel: fp32 -> (hi, lo) bf16 ==================
__global__ void __launch_bounds__(256)
split_kernel(const float* __restrict__ X, __nv_bfloat16* __restrict__ Hi,
             __nv_bfloat16* __restrict__ Lo) {
    const int i = (blockIdx.x * 256 + threadIdx.x) * 4;
    float4 v = *(const float4*)(X + i);
    __nv_bfloat16 h0, h1, h2, h3, l0, l1, l2, l3;
    split2(v.x, h0, l0); split2(v.y, h1, l1);
    split2(v.z, h2, l2); split2(v.w, h3, l3);
    __nv_bfloat162 hp0 = {h0, h1}, hp1 = {h2, h3};
    __nv_bfloat162 lp0 = {l0, l1}, lp1 = {l2, l3};
    *(uint2*)(Hi + i) = make_uint2(*(uint32_t*)&hp0, *(uint32_t*)&hp1);
    *(uint2*)(Lo + i) = make_uint2(*(uint32_t*)&lp0, *(uint32_t*)&lp1);
}

// ============ split-bf16 projection GEMM (2-stage cp.async, z-batched) =====
template <bool DO_ELU, bool SPLIT_OUT>
__global__ void __launch_bounds__(256, 2)
proj_mma_kernel(const __nv_bfloat16* __restrict__ Ah, const __nv_bfloat16* __restrict__ Al,
                const __nv_bfloat16* __restrict__ Wh, const __nv_bfloat16* __restrict__ Wl,
                const float* __restrict__ bias,
                float* __restrict__ Hout,
                __nv_bfloat16* __restrict__ Oh, __nv_bfloat16* __restrict__ Ol) {
    extern __shared__ __align__(128) char dynsm[];
    const uint32_t s0 = smem_u32(dynsm);

    const int tid = threadIdx.x, lane = tid & 31, wid = tid >> 5;
    const int warp_m = wid & 3, warp_n = wid >> 2;
    const int cb = blockIdx.x, rb = blockIdx.y;
    const size_t zoff = (size_t)blockIdx.z * ZSTRIDE;

    const char* Agh = (const char*)(Ah + zoff + (size_t)rb * TS * DDIM);
    const char* Agl = (const char*)(Al + zoff + (size_t)rb * TS * DDIM);
    const char* Wgh = (const char*)(Wh + (size_t)cb * TS * DDIM);
    const char* Wgl = (const char*)(Wl + (size_t)cb * TS * DDIM);

    const int r0 = tid >> 2, p0 = tid & 3;
    const uint32_t so0 = (uint32_t)(r0 * LDAB + p0 * 16);
    const uint32_t so1 = so0 + 64 * LDAB;

    const int q = lane >> 3, rr = lane & 7;
    const uint32_t lds_off = (uint32_t)(((q & 1) * 8 + rr) * LDAB + (q >> 1) * 16);
    const uint32_t am_off = (uint32_t)(warp_m * 32) * LDAB + lds_off;
    const uint32_t wn_off = (uint32_t)(warp_n * 64) * LDAB + lds_off;

    float acc[2][8][4] = {};

    auto load_chunk = [&](int kc, int stg) {
        const size_t g0 = (size_t)r0 * (DDIM * 2) + (size_t)kc * 64 + p0 * 16;
        const size_t g1 = g0 + (size_t)64 * (DDIM * 2);
        const uint32_t b = s0 + stg * PROJSTG;
        CP16(b + so0,                  Agh + g0);
        CP16(b + so1,                  Agh + g1);
        CP16(b + 128 * LDAB + so0,     Agl + g0);
        CP16(b + 128 * LDAB + so1,     Agl + g1);
        CP16(b + 2 * 128 * LDAB + so0, Wgh + g0);
        CP16(b + 2 * 128 * LDAB + so1, Wgh + g1);
        CP16(b + 3 * 128 * LDAB + so0, Wgl + g0);
        CP16(b + 3 * 128 * LDAB + so1, Wgl + g1);
        CPCOMMIT();
    };

    load_chunk(0, 0);
    for (int kc = 0; kc < 16; kc++) {
        if (kc + 1 < 16) load_chunk(kc + 1, (kc + 1) & 1);
        if (kc < 15) { CPWAIT(1); } else { CPWAIT(0); }
        __syncthreads();
        const uint32_t b = s0 + (kc & 1) * PROJSTG;
        const uint32_t ah_base = b + am_off;
        const uint32_t al_base = b + 128 * LDAB + am_off;
        const uint32_t bh_base = b + 2 * 128 * LDAB + wn_off;
        const uint32_t bl_base = b + 3 * 128 * LDAB + wn_off;
#pragma unroll
        for (int kk = 0; kk < 2; kk++) {
            uint32_t ah[2][4], al[2][4];
            ldsm_x4(ah[0], ah_base + kk * 32);
            ldsm_x4(ah[1], ah_base + 16 * LDAB + kk * 32);
            ldsm_x4(al[0], al_base + kk * 32);
            ldsm_x4(al[1], al_base + 16 * LDAB + kk * 32);
#pragma unroll
            for (int n2 = 0; n2 < 4; n2++) {
                uint32_t bh[4], bl[4];
                ldsm_x4(bh, bh_base + n2 * 16 * LDAB + kk * 32);
                ldsm_x4(bl, bl_base + n2 * 16 * LDAB + kk * 32);
#pragma unroll
                for (int mt = 0; mt < 2; mt++)
#pragma unroll
                    for (int u = 0; u < 2; u++) {
                        const int nt = n2 * 2 + u;
                        mma16816(acc[mt][nt], ah[mt], bh[u], bh[u + 2]);
                        mma16816(acc[mt][nt], ah[mt], bl[u], bl[u + 2]);
                        mma16816(acc[mt][nt], al[mt], bh[u], bh[u + 2]);
                    }
            }
        }
        __syncthreads();
    }

    // ---- epilogue ----
    const int cbase = cb * TS + warp_n * 64;
    const int rbase = rb * TS + warp_m * 32 + (lane >> 2);
#pragma unroll
    for (int mt = 0; mt < 2; mt++) {
        const int ra = rbase + mt * 16, rbb = ra + 8;
#pragma unroll
        for (int nt = 0; nt < 8; nt++) {
            const int c = cbase + nt * 8 + (lane & 3) * 2;
            const float bv0 = bias[c], bv1 = bias[c + 1];
            float x00 = acc[mt][nt][0] + bv0, x01 = acc[mt][nt][1] + bv1;
            float x10 = acc[mt][nt][2] + bv0, x11 = acc[mt][nt][3] + bv1;
            if (DO_ELU) {
                x00 = (x00 > 0.0f) ? x00 : expm1f(x00);
                x01 = (x01 > 0.0f) ? x01 : expm1f(x01);
                x10 = (x10 > 0.0f) ? x10 : expm1f(x10);
                x11 = (x11 > 0.0f) ? x11 : expm1f(x11);
            }
            if (SPLIT_OUT) {
                __nv_bfloat16 h0, h1, l0, l1;
                split2(x00, h0, l0); split2(x01, h1, l1);
                __nv_bfloat162 hp = {h0, h1}, lp = {l0, l1};
                *(uint32_t*)(Oh + zoff + (size_t)ra * DDIM + c) = *(uint32_t*)&hp;
                *(uint32_t*)(Ol + zoff + (size_t)ra * DDIM + c) = *(uint32_t*)&lp;
                split2(x10, h0, l0); split2(x11, h1, l1);
                __nv_bfloat162 hq = {h0, h1}, lq = {l0, l1};
                *(uint32_t*)(Oh + zoff + (size_t)rbb * DDIM + c) = *(uint32_t*)&hq;
                *(uint32_t*)(Ol + zoff + (size_t)rbb * DDIM + c) = *(uint32_t*)&lq;
            } else {
                *(float2*)(Hout + zoff + (size_t)ra  * DDIM + c) = make_float2(x00, x01);
                *(float2*)(Hout + zoff + (size_t)rbb * DDIM + c) = make_float2(x10, x11);
            }
        }
    }
}

// ============== similarity tile core (fp8, 3-stage cp.async) ===============
// A, B: fp8 e4m3, row-major [8192, 512] (512 bytes/row), values scaled by 16.
// 8 K-chunks of 64 bytes; two k32 MMA steps per chunk.
__device__ __forceinline__ void sim_tile_mma_fp8(const char* Ag, const char* Bg,
                                                 uint32_t s0,
                                                 float (&acc)[2][8][4],
                                                 int tid, int lane, int warp_m, int warp_n) {
    const int r0 = tid >> 2, p0 = tid & 3;
    const uint32_t so0 = (uint32_t)(r0 * LDAB + p0 * 16);
    const uint32_t so1 = so0 + 64 * LDAB;
    const int q = lane >> 3, rr = lane & 7;
    const uint32_t lds_off = (uint32_t)(((q & 1) * 8 + rr) * LDAB + (q >> 1) * 16);
    const uint32_t am_off = (uint32_t)(warp_m * 32) * LDAB + lds_off;
    const uint32_t bn_off = 128 * LDAB + (uint32_t)(warp_n * 64) * LDAB + lds_off;

    auto load_chunk = [&](int kc, int stg) {
        const size_t g0 = (size_t)r0 * DDIM + (size_t)kc * 64 + p0 * 16;
        const size_t g1 = g0 + (size_t)64 * DDIM;
        const uint32_t b = s0 + stg * SIMSTG;
        CP16(b + so0,              Ag + g0);
        CP16(b + so1,              Ag + g1);
        CP16(b + 128 * LDAB + so0, Bg + g0);
        CP16(b + 128 * LDAB + so1, Bg + g1);
        CPCOMMIT();
    };

    load_chunk(0, 0);
    load_chunk(1, 1);
    int cur = 0;
    for (int kc = 0; kc < 8; kc++) {
        if (kc < 7) { CPWAIT(1); } else { CPWAIT(0); }
        __syncthreads();
        if (kc + 2 < 8) {
            int iss = cur + 2; if (iss >= 3) iss -= 3;
            load_chunk(kc + 2, iss);
        }
        const uint32_t b = s0 + cur * SIMSTG;
        const uint32_t a_base = b + am_off;
        const uint32_t b_base = b + bn_off;
#pragma unroll
        for (int kk = 0; kk < 2; kk++) {
            uint32_t af[2][4];
            ldsm_x4(af[0], a_base + kk * 32);
            ldsm_x4(af[1], a_base + 16 * LDAB + kk * 32);
#pragma unroll
            for (int n2 = 0; n2 < 4; n2++) {
                uint32_t bf[4];
                ldsm_x4(bf, b_base + n2 * 16 * LDAB + kk * 32);
#pragma unroll
                for (int mt = 0; mt < 2; mt++)
#pragma unroll
                    for (int u = 0; u < 2; u++)
                        mma16832_fp8(acc[mt][n2 * 2 + u], af[mt], bf[u], bf[u + 2]);
            }
        }
        cur = (cur + 1 == 3) ? 0 : cur + 1;
    }
    __syncthreads();
}

// exp + row/col reductions (acc holds dot * 256)
__device__ __forceinline__ void sim_reduce(float (&acc)[2][8][4], char* sm,
                                           int lane, int warp_m, int warp_n,
                                           bool do_col) {
    float* rs_sm = (float*)sm;
    float* cs_sm = (float*)(sm + 1024);
    const float C = 2.8853900817779268f / (FP8SCALE * FP8SCALE);  // 2/(ln2*256)
    float rs_acc[2][2] = {};
    float cs2[8][2];
    if (do_col)
#pragma unroll
        for (int nt = 0; nt < 8; nt++) cs2[nt][0] = cs2[nt][1] = 0.0f;

#pragma unroll
    for (int mt = 0; mt < 2; mt++)
#pragma unroll
        for (int nt = 0; nt < 8; nt++) {
            float e0 = fast_exp2(acc[mt][nt][0] * C);
            float e1 = fast_exp2(acc[mt][nt][1] * C);
            float e2 = fast_exp2(acc[mt][nt][2] * C);
            float e3 = fast_exp2(acc[mt][nt][3] * C);
            rs_acc[mt][0] += e0 + e1;
            rs_acc[mt][1] += e2 + e3;
            if (do_col) { cs2[nt][0] += e0 + e2; cs2[nt][1] += e1 + e3; }
        }

#pragma unroll
    for (int mt = 0; mt < 2; mt++)
#pragma unroll
        for (int half = 0; half < 2; half++) {
            float v = rs_acc[mt][half];
            v += __shfl_xor_sync(0xffffffffu, v, 1);
            v += __shfl_xor_sync(0xffffffffu, v, 2);
            if ((lane & 3) == 0) {
                int row = warp_m * 32 + mt * 16 + half * 8 + (lane >> 2);
                rs_sm[row * 2 + warp_n] = v;
            }
        }
    if (do_col) {
#pragma unroll
        for (int nt = 0; nt < 8; nt++)
#pragma unroll
            for (int e = 0; e < 2; e++) {
                float v = cs2[nt][e];
                v += __shfl_xor_sync(0xffffffffu, v, 4);
                v += __shfl_xor_sync(0xffffffffu, v, 8);
                v += __shfl_xor_sync(0xffffffffu, v, 16);
                if (lane < 4) {
                    int col = warp_n * 64 + nt * 8 + lane * 2 + e;
                    cs_sm[warp_m * 128 + col] = v;
                }
            }
    }
    __syncthreads();
}

// ============ unified similarity kernel: all 8256 tiles in ONE launch =======
__global__ void __launch_bounds__(256, 2)
sim_all_kernel(const uint8_t* __restrict__ F1, const uint8_t* __restrict__ F2,
               float* __restrict__ rs11p, float* __restrict__ rs22p,
               float* __restrict__ rs12p, float* __restrict__ cs12p) {
    extern __shared__ __align__(128) char dynsm[];
    const int bid = blockIdx.x;
    const int tid = threadIdx.x, lane = tid & 31, wid = tid >> 5;
    const int warp_m = wid & 3, warp_n = wid >> 2;

    const uint8_t *A, *B;
    float *rsp, *csp;
    int rb, cb;
    bool diag = false, sym;

    if (bid < 2 * NSYM) {
        sym = true;
        const int z = (bid >= NSYM) ? 1 : 0;
        const int idx = bid - z * NSYM;
        int r = (int)(NBLK + 0.5f - sqrtf((NBLK + 0.5f) * (NBLK + 0.5f) - 2.0f * idx));
        if (r < 0) r = 0;
        if (r > NBLK - 1) r = NBLK - 1;
#define TRI_BASE(x) ((x) * NBLK - ((x) * ((x) - 1)) / 2)
        while (r + 1 <= NBLK - 1 && TRI_BASE(r + 1) <= idx) r++;
        while (r > 0 && TRI_BASE(r) > idx) r--;
        rb = r;
        cb = r + (idx - TRI_BASE(r));
#undef TRI_BASE
        A = z ? F2 : F1;
        B = A;
        rsp = z ? rs22p : rs11p;
        csp = nullptr;
        diag = (rb == cb);
    } else {
        sym = false;
        const int idx = bid - 2 * NSYM;
        rb = idx >> 6;
        cb = idx & (NBLK - 1);
        A = F1; B = F2;
        rsp = rs12p; csp = cs12p;
    }

    float acc[2][8][4] = {};
    sim_tile_mma_fp8((const char*)(A + (size_t)rb * TS * DDIM),
                     (const char*)(B + (size_t)cb * TS * DDIM),
                     smem_u32(dynsm), acc, tid, lane, warp_m, warp_n);
    sim_reduce(acc, dynsm, lane, warp_m, warp_n, !diag);

    float* rs_sm = (float*)dynsm;
    float* cs_sm = (float*)(dynsm + 1024);
    if (tid < TS) {
        rsp[(size_t)(rb * TS + tid) * NBLK + cb] = rs_sm[tid * 2] + rs_sm[tid * 2 + 1];
        if (!diag) {
            const float ctot = cs_sm[tid] + cs_sm[128 + tid] +
                               cs_sm[256 + tid] + cs_sm[384 + tid];
            if (sym) rsp[(size_t)(cb * TS + tid) * NBLK + rb] = ctot;
            else     csp[(size_t)(cb * TS + tid) * NBLK + rb] = ctot;
        }
    }
}

// ------------- row L2-normalize (z-batched) -> fp32 + scaled fp8 ----------
__global__ void __launch_bounds__(256)
normalize_kernel(const float* __restrict__ H, float* __restrict__ O1,
                 float* __restrict__ O2, uint8_t* __restrict__ F1,
                 uint8_t* __restrict__ F2) {
    const int z = blockIdx.y;
    const int row  = blockIdx.x * 8 + (threadIdx.x >> 5);
    const int lane = threadIdx.x & 31;
    float* O = z ? O2 : O1;
    uint8_t* F = z ? F2 : F1;
    const float4* hp = (const float4*)(H + (size_t)z * ZSTRIDE + (size_t)row * DDIM);
    float4* op = (float4*)(O + (size_t)row * DDIM);
    float4 v[4];
    float ss = 0.0f;
#pragma unroll
    for (int m = 0; m < 4; m++) {
        v[m] = hp[lane + 32 * m];
        ss += v[m].x * v[m].x + v[m].y * v[m].y + v[m].z * v[m].z + v[m].w * v[m].w;
    }
#pragma unroll
    for (int o = 16; o > 0; o >>= 1) ss += __shfl_xor_sync(0xffffffffu, ss, o);
    const float inv = 1.0f / fmaxf(sqrtf(ss), 1e-12f);
    const float invs = inv * FP8SCALE;
#pragma unroll
    for (int m = 0; m < 4; m++) {
        float4 w = v[m];
        w.x *= inv; w.y *= inv; w.z *= inv; w.w *= inv;
        op[lane + 32 * m] = w;
        __nv_fp8x2_storage_t lo = __nv_cvt_float2_to_fp8x2(
            make_float2(w.x * FP8SCALE, w.y * FP8SCALE), __NV_SATFINITE, __NV_E4M3);
        __nv_fp8x2_storage_t hi = __nv_cvt_float2_to_fp8x2(
            make_float2(w.z * FP8SCALE, w.w * FP8SCALE), __NV_SATFINITE, __NV_E4M3);
        uint32_t pk = (uint32_t)lo | ((uint32_t)hi << 16);
        *(uint32_t*)(F + (size_t)row * DDIM + (lane + 32 * m) * 4) = pk;
    }
    (void)invs;
}

__global__ void __launch_bounds__(256)
d12_kernel(const float* __restrict__ N1, const float* __restrict__ N2,
           float* __restrict__ d12) {
    const int row  = blockIdx.x * 8 + (threadIdx.x >> 5);
    const int lane = threadIdx.x & 31;
    const float4* a = (const float4*)(N1 + (size_t)row * DDIM);
    const float4* b = (const float4*)(N2 + (size_t)row * DDIM);
    float s = 0.0f;
#pragma unroll
    for (int m = 0; m < 4; m++) {
        float4 x = a[lane + 32 * m], y = b[lane + 32 * m];
        s += x.x * y.x + x.y * y.y + x.z * y.z + x.w * y.w;
    }
#pragma unroll
    for (int o = 16; o > 0; o >>= 1) s += __shfl_xor_sync(0xffffffffu, s, o);
    if (lane == 0) d12[row] = s;
}

__global__ void __launch_bounds__(256)
rowloss_kernel(const float* __restrict__ rs11p, const float* __restrict__ rs22p,
               const float* __restrict__ rs12p, const float* __restrict__ cs12p,
               const float* __restrict__ d12, float* __restrict__ loss) {
    const int row  = blockIdx.x * 8 + (threadIdx.x >> 5);
    const int lane = threadIdx.x & 31;
    float s11 = 0.0f, s22 = 0.0f, s12 = 0.0f, c12 = 0.0f;
    for (int m = lane; m < NBLK; m += 32) {
        const size_t o = (size_t)row * NBLK + m;
        s11 += rs11p[o];
        s22 += rs22p[o];
        s12 += rs12p[o];
        c12 += cs12p[o];
    }
#pragma unroll
    for (int o = 16; o > 0; o >>= 1) {
        s11 += __shfl_xor_sync(0xffffffffu, s11, o);
        s22 += __shfl_xor_sync(0xffffffffu, s22, o);
        s12 += __shfl_xor_sync(0xffffffffu, s12, o);
        c12 += __shfl_xor_sync(0xffffffffu, c12, o);
    }
    if (lane == 0) {
        const float E2 = 7.38905609893065f;   // exp(1/tau)
        const float den1 = s11 + s12 - E2;
        const float den2 = s22 + c12 - E2;
        loss[row] = -2.0f * d12[row] + 0.5f * (__logf(den1) + __logf(den2));
    }
}

__global__ void __launch_bounds__(1024)
final_kernel(const float* __restrict__ loss, float* __restrict__ out) {
    __shared__ float sm[1024];
    const int t = threadIdx.x;
    float s = 0.0f;
    for (int i = t; i < NROWS; i += 1024) s += loss[i];
    sm[t] = s;
    __syncthreads();
    for (int o = 512; o > 0; o >>= 1) {
        if (t < o) sm[t] += sm[t + o];
        __syncthreads();
    }
    if (t == 0) out[0] = sm[0] * (1.0f / NROWS);
}

// ---------------- launch ----------------------------------------------------
extern "C" void kernel_launch(void* const* d_in, const int* in_sizes, int n_in,
                              void* d_out, int out_size) {
    const float* pri = (const float*)d_in[0];
    const float* aux = (const float*)d_in[1];
    const float* W1  = (const float*)d_in[2];
    const float* b1  = (const float*)d_in[3];
    const float* W2  = (const float*)d_in[4];
    const float* b2  = (const float*)d_in[5];
    float* out = (float*)d_out;

    __nv_bfloat16 *Zh, *Zl, *Th, *Tl, *W1h, *W1l, *W2h, *W2l;
    uint8_t *F1, *F2;
    float *H, *N1, *N2, *rs11p, *rs22p, *rs12p, *cs12p, *d12, *loss;
    cudaGetSymbolAddress((void**)&Zh,  g_Zh);
    cudaGetSymbolAddress((void**)&Zl,  g_Zl);
    cudaGetSymbolAddress((void**)&Th,  g_Th);
    cudaGetSymbolAddress((void**)&Tl,  g_Tl);
    cudaGetSymbolAddress((void**)&W1h, g_W1h);
    cudaGetSymbolAddress((void**)&W1l, g_W1l);
    cudaGetSymbolAddress((void**)&W2h, g_W2h);
    cudaGetSymbolAddress((void**)&W2l, g_W2l);
    cudaGetSymbolAddress((void**)&H,   g_H);
    cudaGetSymbolAddress((void**)&N1,  g_N1);
    cudaGetSymbolAddress((void**)&N2,  g_N2);
    cudaGetSymbolAddress((void**)&F1,  g_F1);
    cudaGetSymbolAddress((void**)&F2,  g_F2);
    cudaGetSymbolAddress((void**)&rs11p, g_rs11p);
    cudaGetSymbolAddress((void**)&rs22p, g_rs22p);
    cudaGetSymbolAddress((void**)&rs12p, g_rs12p);
    cudaGetSymbolAddress((void**)&cs12p, g_cs12p);
    cudaGetSymbolAddress((void**)&d12,  g_d12);
    cudaGetSymbolAddress((void**)&loss, g_loss);

    const int simSmem  = 3 * SIMSTG;    // 61440
    const int projSmem = 2 * PROJSTG;   // 81920
    cudaFuncSetAttribute(proj_mma_kernel<true,  true >,
                         cudaFuncAttributeMaxDynamicSharedMemorySize, projSmem);
    cudaFuncSetAttribute(proj_mma_kernel<false, false>,
                         cudaFuncAttributeMaxDynamicSharedMemorySize, projSmem);
    cudaFuncSetAttribute(sim_all_kernel,
                         cudaFuncAttributeMaxDynamicSharedMemorySize, simSmem);

    const dim3 pg(DDIM / TS, NROWS / TS, 2);   // (4, 64, 2)
    const int simBlocks = 2 * NSYM + NBLK * NBLK;   // 8256
    const int nW = DDIM * DDIM / 1024;
    const int nZ = NROWS * DDIM / 1024;

    split_kernel<<<nW, 256>>>(W1, W1h, W1l);
    split_kernel<<<nW, 256>>>(W2, W2h, W2l);
    split_kernel<<<nZ, 256>>>(pri, Zh, Zl);
    split_kernel<<<nZ, 256>>>(aux, Zh + ZSTRIDE, Zl + ZSTRIDE);

    proj_mma_kernel<true,  true ><<<pg, 256, projSmem>>>(Zh, Zl, W1h, W1l, b1,
                                                         nullptr, Th, Tl);
    proj_mma_kernel<false, false><<<pg, 256, projSmem>>>(Th, Tl, W2h, W2l, b2,
                                                         H, nullptr, nullptr);
    normalize_kernel<<<dim3(NROWS / 8, 2), 256>>>(H, N1, N2, F1, F2);

    d12_kernel<<<NROWS / 8, 256>>>(N1, N2, d12);

    sim_all_kernel<<<simBlocks, 256, simSmem>>>(F1, F2, rs11p, rs22p, rs12p, cs12p);

    rowloss_kernel<<<NROWS / 8, 256>>>(rs11p, rs22p, rs12p, cs12p, d12, loss);
    final_kernel<<<1, 1024>>>(loss, out);
}